// round 6
// baseline (speedup 1.0000x reference)
#include <cuda_runtime.h>
#include <math.h>
#include <stdint.h>

#define B_    4
#define S_    2048
#define E_    1024
#define H_    8
#define D_    128
#define UVQK_ 4096
#define MTOT  (B_ * S_)

#define ALPHA_F 0.08838834764831845f
#define INV_S_F (1.0f / 2048.0f)

// ---------------------------------------------------------------------------
// Scratch
// ---------------------------------------------------------------------------
__device__ float g_xn[(size_t)MTOT * E_];
__device__ float g_uvqk[(size_t)MTOT * UVQK_];
__device__ float g_attn[(size_t)MTOT * E_];
__device__ float g_nattn[(size_t)MTOT * E_];
__device__ uint32_t g_w1r[(size_t)E_ * UVQK_];   // tf32-rounded uvqk_weight
__device__ uint32_t g_w2r[(size_t)3072 * E_];    // tf32-rounded output_weight

__device__ __forceinline__ float silu_f(float v) {
    return v / (1.0f + __expf(-v));
}
__device__ __forceinline__ uint32_t f2tf(float f) {
    uint32_t u;
    asm("cvt.rna.tf32.f32 %0, %1;" : "=r"(u) : "f"(f));
    return u;
}
__device__ __forceinline__ float rndf(float f) { return __uint_as_float(f2tf(f)); }
__device__ __forceinline__ void mma8(float* c, const uint32_t* a, const uint32_t* b) {
    asm volatile(
        "mma.sync.aligned.m16n8k8.row.col.f32.tf32.tf32.f32 "
        "{%0,%1,%2,%3}, {%4,%5,%6,%7}, {%8,%9}, {%0,%1,%2,%3};"
        : "+f"(c[0]), "+f"(c[1]), "+f"(c[2]), "+f"(c[3])
        : "r"(a[0]), "r"(a[1]), "r"(a[2]), "r"(a[3]), "r"(b[0]), "r"(b[1]));
}
__device__ __forceinline__ uint32_t s2u(const void* p) {
    return (uint32_t)__cvta_generic_to_shared(p);
}
__device__ __forceinline__ void cpa16(uint32_t dst, const void* src) {
    asm volatile("cp.async.cg.shared.global [%0], [%1], 16;" :: "r"(dst), "l"(src));
}
#define CP_COMMIT() asm volatile("cp.async.commit_group;")
#define CP_WAIT(N)  asm volatile("cp.async.wait_group %0;" :: "n"(N))

// ---------------------------------------------------------------------------
// Weight rounding prep (runs inside graph; ~10us)
// ---------------------------------------------------------------------------
#define W1Q (E_ * UVQK_ / 4)
#define W2Q (3072 * E_ / 4)
__global__ __launch_bounds__(256) void round_weights(const float* __restrict__ w1,
                                                     const float* __restrict__ w2) {
    const int idx = blockIdx.x * 256 + threadIdx.x;
    if (idx < W1Q) {
        const float4 v = ((const float4*)w1)[idx];
        uint4 u = {f2tf(v.x), f2tf(v.y), f2tf(v.z), f2tf(v.w)};
        ((uint4*)g_w1r)[idx] = u;
    } else if (idx - W1Q < W2Q) {
        const float4 v = ((const float4*)w2)[idx - W1Q];
        uint4 u = {f2tf(v.x), f2tf(v.y), f2tf(v.z), f2tf(v.w)};
        ((uint4*)g_w2r)[idx - W1Q] = u;
    }
}

// ---------------------------------------------------------------------------
// LayerNorm — outputs rounded to tf32 at store
// ---------------------------------------------------------------------------
__device__ __forceinline__ void ln_row(const float* __restrict__ in,
                                       const float* __restrict__ sc,
                                       const float* __restrict__ bi,
                                       float* __restrict__ out) {
    __shared__ float red[16];
    const size_t row = blockIdx.x;
    const int tid = threadIdx.x;
    const float4 v = ((const float4*)(in + row * E_))[tid];

    float s  = v.x + v.y + v.z + v.w;
    float sq = v.x * v.x + v.y * v.y + v.z * v.z + v.w * v.w;
#pragma unroll
    for (int o = 16; o > 0; o >>= 1) {
        s  += __shfl_xor_sync(0xFFFFFFFFu, s, o);
        sq += __shfl_xor_sync(0xFFFFFFFFu, sq, o);
    }
    const int warp = tid >> 5, lane = tid & 31;
    if (lane == 0) { red[warp] = s; red[8 + warp] = sq; }
    __syncthreads();
    if (tid < 32) {
        float ss = (lane < 8) ? red[lane] : 0.0f;
        float qq = (lane < 8) ? red[8 + lane] : 0.0f;
#pragma unroll
        for (int o = 4; o > 0; o >>= 1) {
            ss += __shfl_xor_sync(0xFFFFFFFFu, ss, o);
            qq += __shfl_xor_sync(0xFFFFFFFFu, qq, o);
        }
        if (lane == 0) { red[0] = ss; red[1] = qq; }
    }
    __syncthreads();
    const float mean = red[0] * (1.0f / (float)E_);
    const float var  = red[1] * (1.0f / (float)E_) - mean * mean;
    const float r    = rsqrtf(var + 1e-6f);

    const float4 scv = ((const float4*)sc)[tid];
    const float4 biv = ((const float4*)bi)[tid];
    float4 o;
    o.x = rndf((v.x - mean) * r * scv.x + biv.x);
    o.y = rndf((v.y - mean) * r * scv.y + biv.y);
    o.z = rndf((v.z - mean) * r * scv.z + biv.z);
    o.w = rndf((v.w - mean) * r * scv.w + biv.w);
    ((float4*)(out + row * E_))[tid] = o;
}

__global__ __launch_bounds__(256) void ln_in_kernel(const float* __restrict__ x,
                                                    const float* __restrict__ sc,
                                                    const float* __restrict__ bi) {
    ln_row(x, sc, bi, g_xn);
}
__global__ __launch_bounds__(256) void ln_attn_kernel(const float* __restrict__ sc,
                                                      const float* __restrict__ bi) {
    ln_row(g_attn, sc, bi, g_nattn);
}

// ---------------------------------------------------------------------------
// GEMM geometry: 128x128 tile, BK=16, 256 threads (8 warps, 2x4), warp 64x32.
//   As[m][20]  (20 % 32 == 4 -> conflict-free), Bs[k][136] (136 % 32 == 8)
// GEMM1: 4-stage cp.async ring, ONE sync per K-step.
// ---------------------------------------------------------------------------
#define APAD 20
#define BPAD 136
#define ASTG (128 * APAD)
#define BSTG (16 * BPAD)
#define G1_SMEM ((4 * ASTG + 4 * BSTG) * 4)

__global__ __launch_bounds__(256) void gemm_uvqk_tc(const float* __restrict__ beta) {
    constexpr int K = E_, N = UVQK_;
    extern __shared__ uint32_t dsm[];
    uint32_t* As = dsm;
    uint32_t* Bs = dsm + 4 * ASTG;

    const int tid = threadIdx.x;
    const int row0 = blockIdx.y * 128, col0 = blockIdx.x * 128;
    const int wid = tid >> 5, lane = tid & 31;
    const int g = lane >> 2, tg = lane & 3;
    const int wm = wid >> 2, wn = wid & 3;
    const uint32_t asb = s2u(As), bsb = s2u(Bs);

    auto docopy = [&](int k0, int buf) {
#pragma unroll
        for (int p = 0; p < 2; p++) {
            const int id = tid + 256 * p;
            const int r = id >> 2, q = id & 3;
            cpa16(asb + (buf * ASTG + r * APAD + q * 4) * 4,
                  &g_xn[(size_t)(row0 + r) * K + k0 + q * 4]);
        }
#pragma unroll
        for (int p = 0; p < 2; p++) {
            const int id = tid + 256 * p;
            const int r = id >> 5, c = id & 31;
            cpa16(bsb + (buf * BSTG + r * BPAD + c * 4) * 4,
                  &g_w1r[(size_t)(k0 + r) * N + col0 + c * 4]);
        }
    };

    float acc[4][4][4];
#pragma unroll
    for (int i = 0; i < 4; i++)
#pragma unroll
        for (int j = 0; j < 4; j++)
#pragma unroll
            for (int r = 0; r < 4; r++) acc[i][j][r] = 0.0f;

    docopy(0, 0);  CP_COMMIT();
    docopy(16, 1); CP_COMMIT();
    docopy(32, 2); CP_COMMIT();

    for (int k0 = 0; k0 < K; k0 += 16) {
        const int it = k0 >> 4;
        const int buf = it & 3;
        CP_WAIT(2);
        __syncthreads();
        if (k0 + 48 < K) docopy(k0 + 48, (it + 3) & 3);
        CP_COMMIT();
#pragma unroll
        for (int kc = 0; kc < 16; kc += 8) {
            uint32_t a[4][4], b[4][2];
#pragma unroll
            for (int mi = 0; mi < 4; mi++) {
                const int ab = buf * ASTG + (wm * 64 + mi * 16 + g) * APAD + kc + tg;
                a[mi][0] = As[ab];
                a[mi][1] = As[ab + 8 * APAD];
                a[mi][2] = As[ab + 4];
                a[mi][3] = As[ab + 8 * APAD + 4];
            }
#pragma unroll
            for (int ni = 0; ni < 4; ni++) {
                const int bb = buf * BSTG + (kc + tg) * BPAD + wn * 32 + ni * 8 + g;
                b[ni][0] = Bs[bb];
                b[ni][1] = Bs[bb + 4 * BPAD];
            }
#pragma unroll
            for (int mi = 0; mi < 4; mi++)
#pragma unroll
                for (int ni = 0; ni < 4; ni++)
                    mma8(acc[mi][ni], a[mi], b[ni]);
        }
    }

#pragma unroll
    for (int mi = 0; mi < 4; mi++) {
        const int r1 = row0 + wm * 64 + mi * 16 + g;
#pragma unroll
        for (int ni = 0; ni < 4; ni++) {
            const int c = col0 + wn * 32 + ni * 8 + 2 * tg;
            const float2 bb = *(const float2*)&beta[c];
            float2 o0 = {rndf(acc[mi][ni][0] + bb.x), rndf(acc[mi][ni][1] + bb.y)};
            float2 o1 = {rndf(acc[mi][ni][2] + bb.x), rndf(acc[mi][ni][3] + bb.y)};
            *(float2*)&g_uvqk[(size_t)r1 * N + c] = o0;
            *(float2*)&g_uvqk[(size_t)(r1 + 8) * N + c] = o1;
        }
    }
}

// ---------------------------------------------------------------------------
// GEMM2: out = x + A[8192,3072] @ W2. A assembled in regs (rounded), B 4-stage.
// ---------------------------------------------------------------------------
#define G2_SMEM ((2 * ASTG + 4 * BSTG) * 4)

__global__ __launch_bounds__(256) void gemm_out_tc(const float* __restrict__ x,
                                                   float* __restrict__ out) {
    constexpr int K = 3072, N = E_;
    extern __shared__ uint32_t dsm2[];
    uint32_t* As = dsm2;
    uint32_t* Bs = dsm2 + 2 * ASTG;
    const uint32_t bsb = s2u(Bs);

    const int tid = threadIdx.x;
    const int row0 = blockIdx.y * 128, col0 = blockIdx.x * 128;
    const int wid = tid >> 5, lane = tid & 31;
    const int g = lane >> 2, tg = lane & 3;
    const int wm = wid >> 2, wn = wid & 3;

    auto copyB = [&](int k0, int buf) {
#pragma unroll
        for (int p = 0; p < 2; p++) {
            const int id = tid + 256 * p;
            const int r = id >> 5, c = id & 31;
            cpa16(bsb + (buf * BSTG + r * BPAD + c * 4) * 4,
                  &g_w2r[(size_t)(k0 + r) * N + col0 + c * 4]);
        }
    };
    auto loadA = [&](int k0, int p) -> uint4 {
        const int id = tid + 256 * p;
        const int r = id >> 2, q = id & 3;
        const int m = row0 + r;
        const int kg = k0 + q * 4;
        const int seg = kg >> 10, kloc = kg & 1023;
        uint4 av;
        if (seg == 0) {
            const float4 t = *(const float4*)&g_uvqk[(size_t)m * UVQK_ + kloc];
            av.x = f2tf(silu_f(t.x)); av.y = f2tf(silu_f(t.y));
            av.z = f2tf(silu_f(t.z)); av.w = f2tf(silu_f(t.w));
        } else if (seg == 1) {
            const float4 t = *(const float4*)&g_attn[(size_t)m * E_ + kloc];
            av.x = __float_as_uint(t.x); av.y = __float_as_uint(t.y);
            av.z = __float_as_uint(t.z); av.w = __float_as_uint(t.w);
        } else {
            const float4 t = *(const float4*)&g_uvqk[(size_t)m * UVQK_ + kloc];
            const float4 nn = *(const float4*)&g_nattn[(size_t)m * E_ + kloc];
            av.x = f2tf(silu_f(t.x) * nn.x);
            av.y = f2tf(silu_f(t.y) * nn.y);
            av.z = f2tf(silu_f(t.z) * nn.z);
            av.w = f2tf(silu_f(t.w) * nn.w);
        }
        return av;
    };

    float acc[4][4][4];
#pragma unroll
    for (int i = 0; i < 4; i++)
#pragma unroll
        for (int j = 0; j < 4; j++)
#pragma unroll
            for (int r = 0; r < 4; r++) acc[i][j][r] = 0.0f;

    uint4 ra[2];
#pragma unroll
    for (int p = 0; p < 2; p++) ra[p] = loadA(0, p);
    copyB(0, 0);  CP_COMMIT();
    copyB(16, 1); CP_COMMIT();
    copyB(32, 2); CP_COMMIT();

    for (int k0 = 0; k0 < K; k0 += 16) {
        const int it = k0 >> 4;
        const int bufB = it & 3, bufA = it & 1;
        // stage A registers into smem (buf last read 2 iters ago)
#pragma unroll
        for (int p = 0; p < 2; p++) {
            const int id = tid + 256 * p;
            const int r = id >> 2, q = id & 3;
            *(uint4*)&As[bufA * ASTG + r * APAD + q * 4] = ra[p];
        }
        if (k0 + 16 < K) {
#pragma unroll
            for (int p = 0; p < 2; p++) ra[p] = loadA(k0 + 16, p);
        }
        CP_WAIT(2);
        __syncthreads();
        if (k0 + 48 < K) copyB(k0 + 48, (it + 3) & 3);
        CP_COMMIT();
#pragma unroll
        for (int kc = 0; kc < 16; kc += 8) {
            uint32_t a[4][4], b[4][2];
#pragma unroll
            for (int mi = 0; mi < 4; mi++) {
                const int ab = bufA * ASTG + (wm * 64 + mi * 16 + g) * APAD + kc + tg;
                a[mi][0] = As[ab];
                a[mi][1] = As[ab + 8 * APAD];
                a[mi][2] = As[ab + 4];
                a[mi][3] = As[ab + 8 * APAD + 4];
            }
#pragma unroll
            for (int ni = 0; ni < 4; ni++) {
                const int bb = bufB * BSTG + (kc + tg) * BPAD + wn * 32 + ni * 8 + g;
                b[ni][0] = Bs[bb];
                b[ni][1] = Bs[bb + 4 * BPAD];
            }
#pragma unroll
            for (int mi = 0; mi < 4; mi++)
#pragma unroll
                for (int ni = 0; ni < 4; ni++)
                    mma8(acc[mi][ni], a[mi], b[ni]);
        }
        __syncthreads();   // A-buf reuse distance is 2: need sync before overwrite
    }

#pragma unroll
    for (int mi = 0; mi < 4; mi++) {
        const int r1 = row0 + wm * 64 + mi * 16 + g;
#pragma unroll
        for (int ni = 0; ni < 4; ni++) {
            const int c = col0 + wn * 32 + ni * 8 + 2 * tg;
            const float2 x0 = *(const float2*)&x[(size_t)r1 * N + c];
            const float2 x1 = *(const float2*)&x[(size_t)(r1 + 8) * N + c];
            float2 o0 = {acc[mi][ni][0] + x0.x, acc[mi][ni][1] + x0.y};
            float2 o1 = {acc[mi][ni][2] + x1.x, acc[mi][ni][3] + x1.y};
            *(float2*)&out[(size_t)r1 * N + c] = o0;
            *(float2*)&out[(size_t)(r1 + 8) * N + c] = o1;
        }
    }
}

// ---------------------------------------------------------------------------
// Attention: 64 q-rows/CTA, 256 threads (8 warps 2x4), double-buffered K/V.
// Stage1: S[64,64] = Q K^T (warp 32x16); Stage2: O[64,128] += P V (warp 32x32)
// ---------------------------------------------------------------------------
#define QPAD 132
#define KVW  (64 * QPAD)          // one K or V tile (stride 132 both)
#define ATTN_WORDS (64 * QPAD + 2 * 2 * KVW + 64 * 68)
#define ATTN_SMEM_BYTES (ATTN_WORDS * 4)
#define PPAD 68

__global__ __launch_bounds__(256) void attn_tc(const int* __restrict__ num_targets) {
    extern __shared__ uint32_t smw[];
    uint32_t* qs = smw;                          // 64 x 132
    uint32_t* kv = qs + 64 * QPAD;               // 2 stages x (K,V) 64x132
    float*    ps = (float*)(kv + 4 * KVW);       // 64 x 68

    const int tid = threadIdx.x;
    const int wid = tid >> 5, lane = tid & 31;
    const int g = lane >> 2, tg = lane & 3;
    const int wm = wid >> 2, wn = wid & 3;

    const int b = blockIdx.z, h = blockIdx.y;
    const int qt = (gridDim.x - 1) - blockIdx.x;  // heavy tiles first
    const int q0 = qt * 64;
    const int limit = S_ - num_targets[b];
    const float* base = g_uvqk + (size_t)b * S_ * UVQK_;
    const uint32_t qsb = s2u(qs), kvb = s2u(kv);

    auto loadKV = [&](int t, int buf) {
        const int k0 = t * 64;
#pragma unroll
        for (int p = 0; p < 8; p++) {
            const int id = tid + 256 * p;
            const int r = id >> 5, c = id & 31;
            const float* rb = &base[(size_t)(k0 + r) * UVQK_ + h * D_ + c * 4];
            cpa16(kvb + (buf * 2 * KVW + r * QPAD + c * 4) * 4, rb + 3072);         // K
            cpa16(kvb + ((buf * 2 + 1) * KVW + r * QPAD + c * 4) * 4, rb + 1024);   // V
        }
    };

    // group 0: Q + KV0 ; group 1: KV1 (or empty)
#pragma unroll
    for (int p = 0; p < 8; p++) {
        const int id = tid + 256 * p;
        const int r = id >> 5, c = id & 31;
        cpa16(qsb + (r * QPAD + c * 4) * 4,
              &base[(size_t)(q0 + r) * UVQK_ + 2048 + h * D_ + c * 4]);
    }
    const int ntile = qt + 1;
    loadKV(0, 0);
    CP_COMMIT();
    if (ntile > 1) loadKV(1, 1);
    CP_COMMIT();

    float oacc[2][4][4];
#pragma unroll
    for (int i = 0; i < 2; i++)
#pragma unroll
        for (int j = 0; j < 4; j++)
#pragma unroll
            for (int r = 0; r < 4; r++) oacc[i][j][r] = 0.0f;

    for (int t = 0; t < ntile; t++) {
        const int k0 = t * 64;
        const int buf = t & 1;
        const uint32_t* ks = kv + buf * 2 * KVW;
        const uint32_t* vs = ks + KVW;

        CP_WAIT(1);
        __syncthreads();

        // ----- Stage 1: S = Q @ K^T  (warp tile 32m x 16n) -----
        float sacc[2][2][4];
#pragma unroll
        for (int i = 0; i < 2; i++)
#pragma unroll
            for (int j = 0; j < 2; j++)
#pragma unroll
                for (int r = 0; r < 4; r++) sacc[i][j][r] = 0.0f;

#pragma unroll
        for (int kc = 0; kc < D_; kc += 8) {
            uint32_t a[2][4], bf[2][2];
#pragma unroll
            for (int mi = 0; mi < 2; mi++) {
                const int ab = (wm * 32 + mi * 16 + g) * QPAD + kc + tg;
                a[mi][0] = qs[ab];
                a[mi][1] = qs[ab + 8 * QPAD];
                a[mi][2] = qs[ab + 4];
                a[mi][3] = qs[ab + 8 * QPAD + 4];
            }
#pragma unroll
            for (int ni = 0; ni < 2; ni++) {
                const int bb = (wn * 16 + ni * 8 + g) * QPAD + kc + tg;
                bf[ni][0] = ks[bb];
                bf[ni][1] = ks[bb + 4];
            }
#pragma unroll
            for (int mi = 0; mi < 2; mi++)
#pragma unroll
                for (int ni = 0; ni < 2; ni++)
                    mma8(sacc[mi][ni], a[mi], bf[ni]);
        }

        // silu + mask + rounded P store
#pragma unroll
        for (int mi = 0; mi < 2; mi++) {
            const int qr = wm * 32 + mi * 16 + g;
            const int qg0 = q0 + qr, qg1 = qg0 + 8;
            const int iq0 = min(qg0, limit), iq1 = min(qg1, limit);
#pragma unroll
            for (int ni = 0; ni < 2; ni++) {
                const int cc = wn * 16 + ni * 8 + 2 * tg;
                const int kg0 = k0 + cc, kg1 = kg0 + 1;
                const int ik0 = min(kg0, limit), ik1 = min(kg1, limit);

                float p00 = ((qg0 == kg0) || (iq0 > ik0)) ? rndf(silu_f(sacc[mi][ni][0] * ALPHA_F) * INV_S_F) : 0.0f;
                float p01 = ((qg0 == kg1) || (iq0 > ik1)) ? rndf(silu_f(sacc[mi][ni][1] * ALPHA_F) * INV_S_F) : 0.0f;
                float p10 = ((qg1 == kg0) || (iq1 > ik0)) ? rndf(silu_f(sacc[mi][ni][2] * ALPHA_F) * INV_S_F) : 0.0f;
                float p11 = ((qg1 == kg1) || (iq1 > ik1)) ? rndf(silu_f(sacc[mi][ni][3] * ALPHA_F) * INV_S_F) : 0.0f;

                float2 u0 = {p00, p01};
                float2 u1 = {p10, p11};
                *(float2*)&ps[qr * PPAD + cc] = u0;
                *(float2*)&ps[(qr + 8) * PPAD + cc] = u1;
            }
        }
        __syncthreads();

        // ----- Stage 2: O += P @ V  (warp tile 32m x 32n) -----
        const uint32_t* psw = (const uint32_t*)ps;
#pragma unroll
        for (int kc = 0; kc < 64; kc += 8) {
            uint32_t a[2][4], bf[4][2];
#pragma unroll
            for (int mi = 0; mi < 2; mi++) {
                const int ab = (wm * 32 + mi * 16 + g) * PPAD + kc + tg;
                a[mi][0] = psw[ab];
                a[mi][1] = psw[ab + 8 * PPAD];
                a[mi][2] = psw[ab + 4];
                a[mi][3] = psw[ab + 8 * PPAD + 4];
            }
#pragma unroll
            for (int ni = 0; ni < 4; ni++) {
                const int bb = (kc + tg) * QPAD + wn * 32 + ni * 8 + g;
                bf[ni][0] = vs[bb];
                bf[ni][1] = vs[bb + 4 * QPAD];
            }
#pragma unroll
            for (int mi = 0; mi < 2; mi++)
#pragma unroll
                for (int ni = 0; ni < 4; ni++)
                    mma8(oacc[mi][ni], a[mi], bf[ni]);
        }
        __syncthreads();   // stage2 reads done; safe to refill this buf

        if (t + 2 < ntile) loadKV(t + 2, buf);
        CP_COMMIT();       // always commit to keep group numbering aligned
    }

    // Epilogue: rounded attn output
#pragma unroll
    for (int mi = 0; mi < 2; mi++) {
        const int r1 = q0 + wm * 32 + mi * 16 + g;
#pragma unroll
        for (int ni = 0; ni < 4; ni++) {
            const int c = h * D_ + wn * 32 + ni * 8 + 2 * tg;
            float2 o0 = {rndf(oacc[mi][ni][0]), rndf(oacc[mi][ni][1])};
            float2 o1 = {rndf(oacc[mi][ni][2]), rndf(oacc[mi][ni][3])};
            *(float2*)&g_attn[(size_t)(b * S_ + r1) * E_ + c] = o0;
            *(float2*)&g_attn[(size_t)(b * S_ + r1 + 8) * E_ + c] = o1;
        }
    }
}

// ---------------------------------------------------------------------------
// Launch
// ---------------------------------------------------------------------------
extern "C" void kernel_launch(void* const* d_in, const int* in_sizes, int n_in,
                              void* d_out, int out_size) {
    const float* x        = (const float*)d_in[0];
    const int*   ntg      = (const int*)d_in[1];
    const float* uvqk_w   = (const float*)d_in[2];
    const float* uvqk_b   = (const float*)d_in[3];
    const float* out_w    = (const float*)d_in[4];
    const float* in_scale = (const float*)d_in[5];
    const float* in_bias  = (const float*)d_in[6];
    const float* out_scale= (const float*)d_in[7];
    const float* out_bias = (const float*)d_in[8];
    float* out = (float*)d_out;

    (void)in_sizes; (void)n_in; (void)out_size;

    static bool attr_set = false;
    if (!attr_set) {
        cudaFuncSetAttribute(attn_tc, cudaFuncAttributeMaxDynamicSharedMemorySize,
                             ATTN_SMEM_BYTES);
        cudaFuncSetAttribute(gemm_uvqk_tc, cudaFuncAttributeMaxDynamicSharedMemorySize,
                             G1_SMEM);
        cudaFuncSetAttribute(gemm_out_tc, cudaFuncAttributeMaxDynamicSharedMemorySize,
                             G2_SMEM);
        attr_set = true;
    }

    round_weights<<<(W1Q + W2Q + 255) / 256, 256>>>(uvqk_w, out_w);
    ln_in_kernel<<<MTOT, 256>>>(x, in_scale, in_bias);
    gemm_uvqk_tc<<<dim3(UVQK_ / 128, MTOT / 128), 256, G1_SMEM>>>(uvqk_b);
    attn_tc<<<dim3(S_ / 64, H_, B_), 256, ATTN_SMEM_BYTES>>>(ntg);
    ln_attn_kernel<<<MTOT, 256>>>(out_scale, out_bias);
    gemm_out_tc<<<dim3(E_ / 128, MTOT / 128), 256, G2_SMEM>>>(x, out);
}

// round 7
// speedup vs baseline: 1.0454x; 1.0454x over previous
#include <cuda_runtime.h>
#include <math.h>
#include <stdint.h>

#define B_    4
#define S_    2048
#define E_    1024
#define H_    8
#define D_    128
#define UVQK_ 4096
#define MTOT  (B_ * S_)

#define ALPHA_F 0.08838834764831845f
#define INV_S_F (1.0f / 2048.0f)

// ---------------------------------------------------------------------------
// Scratch
// ---------------------------------------------------------------------------
__device__ float g_xn[(size_t)MTOT * E_];
__device__ float g_uvqk[(size_t)MTOT * UVQK_];
__device__ float g_attn[(size_t)MTOT * E_];
__device__ float g_nattn[(size_t)MTOT * E_];
__device__ uint32_t g_w1r[(size_t)E_ * UVQK_];   // tf32-rounded uvqk_weight
__device__ uint32_t g_w2r[(size_t)3072 * E_];    // tf32-rounded output_weight

__device__ __forceinline__ float silu_f(float v) {
    return v / (1.0f + __expf(-v));
}
__device__ __forceinline__ uint32_t f2tf(float f) {
    uint32_t u;
    asm("cvt.rna.tf32.f32 %0, %1;" : "=r"(u) : "f"(f));
    return u;
}
__device__ __forceinline__ float rndf(float f) { return __uint_as_float(f2tf(f)); }
__device__ __forceinline__ void mma8(float* c, const uint32_t* a, const uint32_t* b) {
    asm volatile(
        "mma.sync.aligned.m16n8k8.row.col.f32.tf32.tf32.f32 "
        "{%0,%1,%2,%3}, {%4,%5,%6,%7}, {%8,%9}, {%0,%1,%2,%3};"
        : "+f"(c[0]), "+f"(c[1]), "+f"(c[2]), "+f"(c[3])
        : "r"(a[0]), "r"(a[1]), "r"(a[2]), "r"(a[3]), "r"(b[0]), "r"(b[1]));
}
__device__ __forceinline__ uint32_t s2u(const void* p) {
    return (uint32_t)__cvta_generic_to_shared(p);
}
__device__ __forceinline__ void cpa16(uint32_t dst, const void* src) {
    asm volatile("cp.async.cg.shared.global [%0], [%1], 16;" :: "r"(dst), "l"(src));
}
#define CP_COMMIT() asm volatile("cp.async.commit_group;")
#define CP_WAIT(N)  asm volatile("cp.async.wait_group %0;" :: "n"(N))

// ---------------------------------------------------------------------------
// Weight rounding prep
// ---------------------------------------------------------------------------
#define W1Q (E_ * UVQK_ / 4)
#define W2Q (3072 * E_ / 4)
__global__ __launch_bounds__(256) void round_weights(const float* __restrict__ w1,
                                                     const float* __restrict__ w2) {
    const int idx = blockIdx.x * 256 + threadIdx.x;
    if (idx < W1Q) {
        const float4 v = ((const float4*)w1)[idx];
        uint4 u = {f2tf(v.x), f2tf(v.y), f2tf(v.z), f2tf(v.w)};
        ((uint4*)g_w1r)[idx] = u;
    } else if (idx - W1Q < W2Q) {
        const float4 v = ((const float4*)w2)[idx - W1Q];
        uint4 u = {f2tf(v.x), f2tf(v.y), f2tf(v.z), f2tf(v.w)};
        ((uint4*)g_w2r)[idx - W1Q] = u;
    }
}

// ---------------------------------------------------------------------------
// LayerNorm — outputs rounded to tf32 at store
// ---------------------------------------------------------------------------
__device__ __forceinline__ void ln_row(const float* __restrict__ in,
                                       const float* __restrict__ sc,
                                       const float* __restrict__ bi,
                                       float* __restrict__ out) {
    __shared__ float red[16];
    const size_t row = blockIdx.x;
    const int tid = threadIdx.x;
    const float4 v = ((const float4*)(in + row * E_))[tid];

    float s  = v.x + v.y + v.z + v.w;
    float sq = v.x * v.x + v.y * v.y + v.z * v.z + v.w * v.w;
#pragma unroll
    for (int o = 16; o > 0; o >>= 1) {
        s  += __shfl_xor_sync(0xFFFFFFFFu, s, o);
        sq += __shfl_xor_sync(0xFFFFFFFFu, sq, o);
    }
    const int warp = tid >> 5, lane = tid & 31;
    if (lane == 0) { red[warp] = s; red[8 + warp] = sq; }
    __syncthreads();
    if (tid < 32) {
        float ss = (lane < 8) ? red[lane] : 0.0f;
        float qq = (lane < 8) ? red[8 + lane] : 0.0f;
#pragma unroll
        for (int o = 4; o > 0; o >>= 1) {
            ss += __shfl_xor_sync(0xFFFFFFFFu, ss, o);
            qq += __shfl_xor_sync(0xFFFFFFFFu, qq, o);
        }
        if (lane == 0) { red[0] = ss; red[1] = qq; }
    }
    __syncthreads();
    const float mean = red[0] * (1.0f / (float)E_);
    const float var  = red[1] * (1.0f / (float)E_) - mean * mean;
    const float r    = rsqrtf(var + 1e-6f);

    const float4 scv = ((const float4*)sc)[tid];
    const float4 biv = ((const float4*)bi)[tid];
    float4 o;
    o.x = rndf((v.x - mean) * r * scv.x + biv.x);
    o.y = rndf((v.y - mean) * r * scv.y + biv.y);
    o.z = rndf((v.z - mean) * r * scv.z + biv.z);
    o.w = rndf((v.w - mean) * r * scv.w + biv.w);
    ((float4*)(out + row * E_))[tid] = o;
}

__global__ __launch_bounds__(256) void ln_in_kernel(const float* __restrict__ x,
                                                    const float* __restrict__ sc,
                                                    const float* __restrict__ bi) {
    ln_row(x, sc, bi, g_xn);
}
__global__ __launch_bounds__(256) void ln_attn_kernel(const float* __restrict__ sc,
                                                      const float* __restrict__ bi) {
    ln_row(g_attn, sc, bi, g_nattn);
}

// ---------------------------------------------------------------------------
// GEMM geometry (unchanged from R6): 128x128 tile, BK=16, 256 threads, 4-stage
// ---------------------------------------------------------------------------
#define APAD 20
#define BPAD 136
#define ASTG (128 * APAD)
#define BSTG (16 * BPAD)
#define G1_SMEM ((4 * ASTG + 4 * BSTG) * 4)

__global__ __launch_bounds__(256) void gemm_uvqk_tc(const float* __restrict__ beta) {
    constexpr int K = E_, N = UVQK_;
    extern __shared__ uint32_t dsm[];
    uint32_t* As = dsm;
    uint32_t* Bs = dsm + 4 * ASTG;

    const int tid = threadIdx.x;
    const int row0 = blockIdx.y * 128, col0 = blockIdx.x * 128;
    const int wid = tid >> 5, lane = tid & 31;
    const int g = lane >> 2, tg = lane & 3;
    const int wm = wid >> 2, wn = wid & 3;
    const uint32_t asb = s2u(As), bsb = s2u(Bs);

    auto docopy = [&](int k0, int buf) {
#pragma unroll
        for (int p = 0; p < 2; p++) {
            const int id = tid + 256 * p;
            const int r = id >> 2, q = id & 3;
            cpa16(asb + (buf * ASTG + r * APAD + q * 4) * 4,
                  &g_xn[(size_t)(row0 + r) * K + k0 + q * 4]);
        }
#pragma unroll
        for (int p = 0; p < 2; p++) {
            const int id = tid + 256 * p;
            const int r = id >> 5, c = id & 31;
            cpa16(bsb + (buf * BSTG + r * BPAD + c * 4) * 4,
                  &g_w1r[(size_t)(k0 + r) * N + col0 + c * 4]);
        }
    };

    float acc[4][4][4];
#pragma unroll
    for (int i = 0; i < 4; i++)
#pragma unroll
        for (int j = 0; j < 4; j++)
#pragma unroll
            for (int r = 0; r < 4; r++) acc[i][j][r] = 0.0f;

    docopy(0, 0);  CP_COMMIT();
    docopy(16, 1); CP_COMMIT();
    docopy(32, 2); CP_COMMIT();

    for (int k0 = 0; k0 < K; k0 += 16) {
        const int it = k0 >> 4;
        const int buf = it & 3;
        CP_WAIT(2);
        __syncthreads();
        if (k0 + 48 < K) docopy(k0 + 48, (it + 3) & 3);
        CP_COMMIT();
#pragma unroll
        for (int kc = 0; kc < 16; kc += 8) {
            uint32_t a[4][4], b[4][2];
#pragma unroll
            for (int mi = 0; mi < 4; mi++) {
                const int ab = buf * ASTG + (wm * 64 + mi * 16 + g) * APAD + kc + tg;
                a[mi][0] = As[ab];
                a[mi][1] = As[ab + 8 * APAD];
                a[mi][2] = As[ab + 4];
                a[mi][3] = As[ab + 8 * APAD + 4];
            }
#pragma unroll
            for (int ni = 0; ni < 4; ni++) {
                const int bb = buf * BSTG + (kc + tg) * BPAD + wn * 32 + ni * 8 + g;
                b[ni][0] = Bs[bb];
                b[ni][1] = Bs[bb + 4 * BPAD];
            }
#pragma unroll
            for (int mi = 0; mi < 4; mi++)
#pragma unroll
                for (int ni = 0; ni < 4; ni++)
                    mma8(acc[mi][ni], a[mi], b[ni]);
        }
    }

#pragma unroll
    for (int mi = 0; mi < 4; mi++) {
        const int r1 = row0 + wm * 64 + mi * 16 + g;
#pragma unroll
        for (int ni = 0; ni < 4; ni++) {
            const int c = col0 + wn * 32 + ni * 8 + 2 * tg;
            const float2 bb = *(const float2*)&beta[c];
            float2 o0 = {rndf(acc[mi][ni][0] + bb.x), rndf(acc[mi][ni][1] + bb.y)};
            float2 o1 = {rndf(acc[mi][ni][2] + bb.x), rndf(acc[mi][ni][3] + bb.y)};
            *(float2*)&g_uvqk[(size_t)r1 * N + c] = o0;
            *(float2*)&g_uvqk[(size_t)(r1 + 8) * N + c] = o1;
        }
    }
}

// ---------------------------------------------------------------------------
// GEMM2 (unchanged from R6)
// ---------------------------------------------------------------------------
#define G2_SMEM ((2 * ASTG + 4 * BSTG) * 4)

__global__ __launch_bounds__(256) void gemm_out_tc(const float* __restrict__ x,
                                                   float* __restrict__ out) {
    constexpr int K = 3072, N = E_;
    extern __shared__ uint32_t dsm2[];
    uint32_t* As = dsm2;
    uint32_t* Bs = dsm2 + 2 * ASTG;
    const uint32_t bsb = s2u(Bs);

    const int tid = threadIdx.x;
    const int row0 = blockIdx.y * 128, col0 = blockIdx.x * 128;
    const int wid = tid >> 5, lane = tid & 31;
    const int g = lane >> 2, tg = lane & 3;
    const int wm = wid >> 2, wn = wid & 3;

    auto copyB = [&](int k0, int buf) {
#pragma unroll
        for (int p = 0; p < 2; p++) {
            const int id = tid + 256 * p;
            const int r = id >> 5, c = id & 31;
            cpa16(bsb + (buf * BSTG + r * BPAD + c * 4) * 4,
                  &g_w2r[(size_t)(k0 + r) * N + col0 + c * 4]);
        }
    };
    auto loadA = [&](int k0, int p) -> uint4 {
        const int id = tid + 256 * p;
        const int r = id >> 2, q = id & 3;
        const int m = row0 + r;
        const int kg = k0 + q * 4;
        const int seg = kg >> 10, kloc = kg & 1023;
        uint4 av;
        if (seg == 0) {
            const float4 t = *(const float4*)&g_uvqk[(size_t)m * UVQK_ + kloc];
            av.x = f2tf(silu_f(t.x)); av.y = f2tf(silu_f(t.y));
            av.z = f2tf(silu_f(t.z)); av.w = f2tf(silu_f(t.w));
        } else if (seg == 1) {
            const float4 t = *(const float4*)&g_attn[(size_t)m * E_ + kloc];
            av.x = __float_as_uint(t.x); av.y = __float_as_uint(t.y);
            av.z = __float_as_uint(t.z); av.w = __float_as_uint(t.w);
        } else {
            const float4 t = *(const float4*)&g_uvqk[(size_t)m * UVQK_ + kloc];
            const float4 nn = *(const float4*)&g_nattn[(size_t)m * E_ + kloc];
            av.x = f2tf(silu_f(t.x) * nn.x);
            av.y = f2tf(silu_f(t.y) * nn.y);
            av.z = f2tf(silu_f(t.z) * nn.z);
            av.w = f2tf(silu_f(t.w) * nn.w);
        }
        return av;
    };

    float acc[4][4][4];
#pragma unroll
    for (int i = 0; i < 4; i++)
#pragma unroll
        for (int j = 0; j < 4; j++)
#pragma unroll
            for (int r = 0; r < 4; r++) acc[i][j][r] = 0.0f;

    uint4 ra[2];
#pragma unroll
    for (int p = 0; p < 2; p++) ra[p] = loadA(0, p);
    copyB(0, 0);  CP_COMMIT();
    copyB(16, 1); CP_COMMIT();
    copyB(32, 2); CP_COMMIT();

    for (int k0 = 0; k0 < K; k0 += 16) {
        const int it = k0 >> 4;
        const int bufB = it & 3, bufA = it & 1;
#pragma unroll
        for (int p = 0; p < 2; p++) {
            const int id = tid + 256 * p;
            const int r = id >> 2, q = id & 3;
            *(uint4*)&As[bufA * ASTG + r * APAD + q * 4] = ra[p];
        }
        if (k0 + 16 < K) {
#pragma unroll
            for (int p = 0; p < 2; p++) ra[p] = loadA(k0 + 16, p);
        }
        CP_WAIT(2);
        __syncthreads();
        if (k0 + 48 < K) copyB(k0 + 48, (it + 3) & 3);
        CP_COMMIT();
#pragma unroll
        for (int kc = 0; kc < 16; kc += 8) {
            uint32_t a[4][4], b[4][2];
#pragma unroll
            for (int mi = 0; mi < 4; mi++) {
                const int ab = bufA * ASTG + (wm * 64 + mi * 16 + g) * APAD + kc + tg;
                a[mi][0] = As[ab];
                a[mi][1] = As[ab + 8 * APAD];
                a[mi][2] = As[ab + 4];
                a[mi][3] = As[ab + 8 * APAD + 4];
            }
#pragma unroll
            for (int ni = 0; ni < 4; ni++) {
                const int bb = bufB * BSTG + (kc + tg) * BPAD + wn * 32 + ni * 8 + g;
                b[ni][0] = Bs[bb];
                b[ni][1] = Bs[bb + 4 * BPAD];
            }
#pragma unroll
            for (int mi = 0; mi < 4; mi++)
#pragma unroll
                for (int ni = 0; ni < 4; ni++)
                    mma8(acc[mi][ni], a[mi], b[ni]);
        }
        __syncthreads();
    }

#pragma unroll
    for (int mi = 0; mi < 4; mi++) {
        const int r1 = row0 + wm * 64 + mi * 16 + g;
#pragma unroll
        for (int ni = 0; ni < 4; ni++) {
            const int c = col0 + wn * 32 + ni * 8 + 2 * tg;
            const float2 x0 = *(const float2*)&x[(size_t)r1 * N + c];
            const float2 x1 = *(const float2*)&x[(size_t)(r1 + 8) * N + c];
            float2 o0 = {acc[mi][ni][0] + x0.x, acc[mi][ni][1] + x0.y};
            float2 o1 = {acc[mi][ni][2] + x1.x, acc[mi][ni][3] + x1.y};
            *(float2*)&out[(size_t)r1 * N + c] = o0;
            *(float2*)&out[(size_t)(r1 + 8) * N + c] = o1;
        }
    }
}

// ---------------------------------------------------------------------------
// Attention v3: 128 q-rows/CTA, 512 threads (16 warps, 4x4).
// K double-buffered; V single-buffered, overlapped with next stage1.
// Stage1: S[128,64] = Q K^T  (warp 32x16)
// Stage2: O[128,128] += P V  (warp 32x32)
// smem: Q 128x132, K 2x64x132, V 64x132, P 128x68  = ~199 KB, 1 CTA/SM.
// ---------------------------------------------------------------------------
#define QPAD 132
#define PPAD 68
#define AT_Q  (128 * QPAD)
#define AT_K  (64 * QPAD)
#define ATTN_WORDS (AT_Q + 2 * AT_K + AT_K + 128 * PPAD)
#define ATTN_SMEM_BYTES (ATTN_WORDS * 4)

__global__ __launch_bounds__(512) void attn_tc(const int* __restrict__ num_targets) {
    extern __shared__ uint32_t smw[];
    uint32_t* qs = smw;                   // 128 x 132
    uint32_t* kb = qs + AT_Q;             // 2 x 64 x 132
    uint32_t* vs = kb + 2 * AT_K;         // 64 x 132
    float*    ps = (float*)(vs + AT_K);   // 128 x 68

    const int tid = threadIdx.x;
    const int wid = tid >> 5, lane = tid & 31;
    const int g = lane >> 2, tg = lane & 3;
    const int wm = wid >> 2, wn = wid & 3;

    const int b = blockIdx.z, h = blockIdx.y;
    const int qt = (gridDim.x - 1) - blockIdx.x;   // heavy tiles first
    const int q0 = qt * 128;
    const int limit = S_ - num_targets[b];
    const float* base = g_uvqk + (size_t)b * S_ * UVQK_;
    const uint32_t qsb = s2u(qs), kbb = s2u(kb), vsb = s2u(vs);

    auto loadK = [&](int t, int buf) {
        const int k0 = t * 64;
#pragma unroll
        for (int p = 0; p < 4; p++) {
            const int id = tid + 512 * p;
            const int r = id >> 5, c = id & 31;
            cpa16(kbb + (buf * AT_K + r * QPAD + c * 4) * 4,
                  &base[(size_t)(k0 + r) * UVQK_ + 3072 + h * D_ + c * 4]);
        }
    };
    auto loadV = [&](int t) {
        const int k0 = t * 64;
#pragma unroll
        for (int p = 0; p < 4; p++) {
            const int id = tid + 512 * p;
            const int r = id >> 5, c = id & 31;
            cpa16(vsb + (r * QPAD + c * 4) * 4,
                  &base[(size_t)(k0 + r) * UVQK_ + 1024 + h * D_ + c * 4]);
        }
    };

    // g0 = {Q, K0, V0}; g1 = {K1}
#pragma unroll
    for (int p = 0; p < 8; p++) {
        const int id = tid + 512 * p;
        const int r = id >> 5, c = id & 31;
        cpa16(qsb + (r * QPAD + c * 4) * 4,
              &base[(size_t)(q0 + r) * UVQK_ + 2048 + h * D_ + c * 4]);
    }
    const int ntile = 2 * qt + 2;
    loadK(0, 0);
    loadV(0);
    CP_COMMIT();
    if (ntile > 1) loadK(1, 1);
    CP_COMMIT();

    float oacc[2][4][4];
#pragma unroll
    for (int i = 0; i < 2; i++)
#pragma unroll
        for (int j = 0; j < 4; j++)
#pragma unroll
            for (int r = 0; r < 4; r++) oacc[i][j][r] = 0.0f;

    for (int t = 0; t < ntile; t++) {
        const int k0 = t * 64;
        const uint32_t* ks = kb + (t & 1) * AT_K;

        // drains through g_{2t} (contains V(t) and K(t)); K(t+1) stays in flight
        CP_WAIT(1);
        __syncthreads();

        // ----- Stage 1: S = Q @ K^T  (warp tile 32m x 16n) -----
        float sacc[2][2][4];
#pragma unroll
        for (int i = 0; i < 2; i++)
#pragma unroll
            for (int j = 0; j < 2; j++)
#pragma unroll
                for (int r = 0; r < 4; r++) sacc[i][j][r] = 0.0f;

#pragma unroll
        for (int kc = 0; kc < D_; kc += 8) {
            uint32_t a[2][4], bf[2][2];
#pragma unroll
            for (int mi = 0; mi < 2; mi++) {
                const int ab = (wm * 32 + mi * 16 + g) * QPAD + kc + tg;
                a[mi][0] = qs[ab];
                a[mi][1] = qs[ab + 8 * QPAD];
                a[mi][2] = qs[ab + 4];
                a[mi][3] = qs[ab + 8 * QPAD + 4];
            }
#pragma unroll
            for (int ni = 0; ni < 2; ni++) {
                const int bb = (wn * 16 + ni * 8 + g) * QPAD + kc + tg;
                bf[ni][0] = ks[bb];
                bf[ni][1] = ks[bb + 4];
            }
#pragma unroll
            for (int mi = 0; mi < 2; mi++)
#pragma unroll
                for (int ni = 0; ni < 2; ni++)
                    mma8(sacc[mi][ni], a[mi], bf[ni]);
        }

        // silu + mask + rounded P store
#pragma unroll
        for (int mi = 0; mi < 2; mi++) {
            const int qr = wm * 32 + mi * 16 + g;
            const int qg0 = q0 + qr, qg1 = qg0 + 8;
            const int iq0 = min(qg0, limit), iq1 = min(qg1, limit);
#pragma unroll
            for (int ni = 0; ni < 2; ni++) {
                const int cc = wn * 16 + ni * 8 + 2 * tg;
                const int kg0 = k0 + cc, kg1 = kg0 + 1;
                const int ik0 = min(kg0, limit), ik1 = min(kg1, limit);

                float p00 = ((qg0 == kg0) || (iq0 > ik0)) ? rndf(silu_f(sacc[mi][ni][0] * ALPHA_F) * INV_S_F) : 0.0f;
                float p01 = ((qg0 == kg1) || (iq0 > ik1)) ? rndf(silu_f(sacc[mi][ni][1] * ALPHA_F) * INV_S_F) : 0.0f;
                float p10 = ((qg1 == kg0) || (iq1 > ik0)) ? rndf(silu_f(sacc[mi][ni][2] * ALPHA_F) * INV_S_F) : 0.0f;
                float p11 = ((qg1 == kg1) || (iq1 > ik1)) ? rndf(silu_f(sacc[mi][ni][3] * ALPHA_F) * INV_S_F) : 0.0f;

                float2 u0 = {p00, p01};
                float2 u1 = {p10, p11};
                *(float2*)&ps[qr * PPAD + cc] = u0;
                *(float2*)&ps[(qr + 8) * PPAD + cc] = u1;
            }
        }
        __syncthreads();

        // ----- Stage 2: O += P @ V  (warp tile 32m x 32n) -----
        const uint32_t* psw = (const uint32_t*)ps;
#pragma unroll
        for (int kc = 0; kc < 64; kc += 8) {
            uint32_t a[2][4], bf[4][2];
#pragma unroll
            for (int mi = 0; mi < 2; mi++) {
                const int ab = (wm * 32 + mi * 16 + g) * PPAD + kc + tg;
                a[mi][0] = psw[ab];
                a[mi][1] = psw[ab + 8 * PPAD];
                a[mi][2] = psw[ab + 4];
                a[mi][3] = psw[ab + 8 * PPAD + 4];
            }
#pragma unroll
            for (int ni = 0; ni < 4; ni++) {
                const int bb = (kc + tg) * QPAD + wn * 32 + ni * 8 + g;
                bf[ni][0] = vs[bb];
                bf[ni][1] = vs[bb + 4 * QPAD];
            }
#pragma unroll
            for (int mi = 0; mi < 2; mi++)
#pragma unroll
                for (int ni = 0; ni < 4; ni++)
                    mma8(oacc[mi][ni], a[mi], bf[ni]);
        }
        __syncthreads();   // all stage2 V reads done

        // g_{2t+2} = {V(t+1)}: overlaps next stage1 (which only needs K,Q,P)
        if (t + 1 < ntile) loadV(t + 1);
        CP_COMMIT();
        // g_{2t+3} = {K(t+2)} into buffer (t&1): last read in stage1(t), done
        if (t + 2 < ntile) loadK(t + 2, t & 1);
        CP_COMMIT();
    }

    // Epilogue: rounded attn output
#pragma unroll
    for (int mi = 0; mi < 2; mi++) {
        const int r1 = q0 + wm * 32 + mi * 16 + g;
#pragma unroll
        for (int ni = 0; ni < 4; ni++) {
            const int c = h * D_ + wn * 32 + ni * 8 + 2 * tg;
            float2 o0 = {rndf(oacc[mi][ni][0]), rndf(oacc[mi][ni][1])};
            float2 o1 = {rndf(oacc[mi][ni][2]), rndf(oacc[mi][ni][3])};
            *(float2*)&g_attn[(size_t)(b * S_ + r1) * E_ + c] = o0;
            *(float2*)&g_attn[(size_t)(b * S_ + r1 + 8) * E_ + c] = o1;
        }
    }
}

// ---------------------------------------------------------------------------
// Launch
// ---------------------------------------------------------------------------
extern "C" void kernel_launch(void* const* d_in, const int* in_sizes, int n_in,
                              void* d_out, int out_size) {
    const float* x        = (const float*)d_in[0];
    const int*   ntg      = (const int*)d_in[1];
    const float* uvqk_w   = (const float*)d_in[2];
    const float* uvqk_b   = (const float*)d_in[3];
    const float* out_w    = (const float*)d_in[4];
    const float* in_scale = (const float*)d_in[5];
    const float* in_bias  = (const float*)d_in[6];
    const float* out_scale= (const float*)d_in[7];
    const float* out_bias = (const float*)d_in[8];
    float* out = (float*)d_out;

    (void)in_sizes; (void)n_in; (void)out_size;

    static bool attr_set = false;
    if (!attr_set) {
        cudaFuncSetAttribute(attn_tc, cudaFuncAttributeMaxDynamicSharedMemorySize,
                             ATTN_SMEM_BYTES);
        cudaFuncSetAttribute(gemm_uvqk_tc, cudaFuncAttributeMaxDynamicSharedMemorySize,
                             G1_SMEM);
        cudaFuncSetAttribute(gemm_out_tc, cudaFuncAttributeMaxDynamicSharedMemorySize,
                             G2_SMEM);
        attr_set = true;
    }

    round_weights<<<(W1Q + W2Q + 255) / 256, 256>>>(uvqk_w, out_w);
    ln_in_kernel<<<MTOT, 256>>>(x, in_scale, in_bias);
    gemm_uvqk_tc<<<dim3(UVQK_ / 128, MTOT / 128), 256, G1_SMEM>>>(uvqk_b);
    attn_tc<<<dim3(S_ / 128, H_, B_), 512, ATTN_SMEM_BYTES>>>(ntg);
    ln_attn_kernel<<<MTOT, 256>>>(out_scale, out_bias);
    gemm_out_tc<<<dim3(E_ / 128, MTOT / 128), 256, G2_SMEM>>>(x, out);
}

// round 9
// speedup vs baseline: 1.4942x; 1.4293x over previous
#include <cuda_runtime.h>
#include <cuda_fp16.h>
#include <math.h>
#include <stdint.h>

#define B_    4
#define S_    2048
#define E_    1024
#define H_    8
#define D_    128
#define UVQK_ 4096
#define MTOT  (B_ * S_)

#define ALPHA_F 0.08838834764831845f
#define INV_S_F (1.0f / 2048.0f)

// ---------------------------------------------------------------------------
// Scratch (all matmul operands in fp16; V kept fp32 for stage2)
// ---------------------------------------------------------------------------
__device__ __half g_xnh[(size_t)MTOT * E_];        // 16 MB
__device__ __half g_uvqkh[(size_t)MTOT * UVQK_];   // 64 MB
__device__ __half g_attnh[(size_t)MTOT * E_];      // 16 MB
__device__ __half g_nattnh[(size_t)MTOT * E_];     // 16 MB
__device__ float  g_vf[(size_t)MTOT * E_];         // 32 MB (fp32 V for stage2)
__device__ __half g_w1h[(size_t)UVQK_ * E_];       // [n=4096][k=1024]
__device__ __half g_w2h[(size_t)E_ * 3072];        // [n=1024][k=3072]

__device__ __forceinline__ float silu_f(float v) {
    return v / (1.0f + __expf(-v));
}
__device__ __forceinline__ uint32_t f2tf(float f) {
    uint32_t u;
    asm("cvt.rna.tf32.f32 %0, %1;" : "=r"(u) : "f"(f));
    return u;
}
__device__ __forceinline__ float rndf(float f) { return __uint_as_float(f2tf(f)); }

// tf32 m16n8k8 (stage2 of attention)
__device__ __forceinline__ void mma8(float* c, const uint32_t* a, const uint32_t* b) {
    asm volatile(
        "mma.sync.aligned.m16n8k8.row.col.f32.tf32.tf32.f32 "
        "{%0,%1,%2,%3}, {%4,%5,%6,%7}, {%8,%9}, {%0,%1,%2,%3};"
        : "+f"(c[0]), "+f"(c[1]), "+f"(c[2]), "+f"(c[3])
        : "r"(a[0]), "r"(a[1]), "r"(a[2]), "r"(a[3]), "r"(b[0]), "r"(b[1]));
}
// fp16 m16n8k16, fp32 accumulate
__device__ __forceinline__ void mma16(float* c, const uint32_t* a, const uint32_t* b) {
    asm volatile(
        "mma.sync.aligned.m16n8k16.row.col.f32.f16.f16.f32 "
        "{%0,%1,%2,%3}, {%4,%5,%6,%7}, {%8,%9}, {%0,%1,%2,%3};"
        : "+f"(c[0]), "+f"(c[1]), "+f"(c[2]), "+f"(c[3])
        : "r"(a[0]), "r"(a[1]), "r"(a[2]), "r"(a[3]), "r"(b[0]), "r"(b[1]));
}
__device__ __forceinline__ uint32_t s2u(const void* p) {
    return (uint32_t)__cvta_generic_to_shared(p);
}
__device__ __forceinline__ void cpa16(uint32_t dst, const void* src) {
    asm volatile("cp.async.cg.shared.global [%0], [%1], 16;" :: "r"(dst), "l"(src));
}
#define CP_COMMIT() asm volatile("cp.async.commit_group;")
#define CP_WAIT(N)  asm volatile("cp.async.wait_group %0;" :: "n"(N))

__device__ __forceinline__ uint32_t h2pack(float a, float b) {
    __half2 h = __float22half2_rn(make_float2(a, b));
    return *(uint32_t*)&h;
}
__device__ __forceinline__ float2 h2unpack(uint32_t u) {
    return __half22float2(*(__half2*)&u);
}
__device__ __forceinline__ uint32_t silu_h2(uint32_t u) {
    float2 f = h2unpack(u);
    return h2pack(silu_f(f.x), silu_f(f.y));
}

// ---------------------------------------------------------------------------
// Weight prep: transpose [K][N] fp32 -> [N][K] fp16 (tiled, coalesced)
// ---------------------------------------------------------------------------
__global__ __launch_bounds__(256) void transpose_half(const float* __restrict__ src,
                                                      __half* __restrict__ dst,
                                                      int K, int N) {
    __shared__ float t[32][33];
    const int k0 = blockIdx.x * 32, n0 = blockIdx.y * 32;
    const int tx = threadIdx.x, ty = threadIdx.y;  // 32 x 8
#pragma unroll
    for (int j = 0; j < 4; j++)
        t[ty + 8 * j][tx] = src[(size_t)(k0 + ty + 8 * j) * N + n0 + tx];
    __syncthreads();
#pragma unroll
    for (int j = 0; j < 4; j++)
        dst[(size_t)(n0 + ty + 8 * j) * K + k0 + tx] = __float2half(t[tx][ty + 8 * j]);
}

// ---------------------------------------------------------------------------
// LayerNorm: in fp32 -> out fp16  (ln_in)
// ---------------------------------------------------------------------------
__global__ __launch_bounds__(256) void ln_in_kernel(const float* __restrict__ x,
                                                    const float* __restrict__ sc,
                                                    const float* __restrict__ bi) {
    __shared__ float red[16];
    const size_t row = blockIdx.x;
    const int tid = threadIdx.x;
    const float4 v = ((const float4*)(x + row * E_))[tid];

    float s  = v.x + v.y + v.z + v.w;
    float sq = v.x * v.x + v.y * v.y + v.z * v.z + v.w * v.w;
#pragma unroll
    for (int o = 16; o > 0; o >>= 1) {
        s  += __shfl_xor_sync(0xFFFFFFFFu, s, o);
        sq += __shfl_xor_sync(0xFFFFFFFFu, sq, o);
    }
    const int warp = tid >> 5, lane = tid & 31;
    if (lane == 0) { red[warp] = s; red[8 + warp] = sq; }
    __syncthreads();
    if (tid < 32) {
        float ss = (lane < 8) ? red[lane] : 0.0f;
        float qq = (lane < 8) ? red[8 + lane] : 0.0f;
#pragma unroll
        for (int o = 4; o > 0; o >>= 1) {
            ss += __shfl_xor_sync(0xFFFFFFFFu, ss, o);
            qq += __shfl_xor_sync(0xFFFFFFFFu, qq, o);
        }
        if (lane == 0) { red[0] = ss; red[1] = qq; }
    }
    __syncthreads();
    const float mean = red[0] * (1.0f / (float)E_);
    const float var  = red[1] * (1.0f / (float)E_) - mean * mean;
    const float r    = rsqrtf(var + 1e-6f);

    const float4 scv = ((const float4*)sc)[tid];
    const float4 biv = ((const float4*)bi)[tid];
    uint2 o;
    o.x = h2pack((v.x - mean) * r * scv.x + biv.x, (v.y - mean) * r * scv.y + biv.y);
    o.y = h2pack((v.z - mean) * r * scv.z + biv.z, (v.w - mean) * r * scv.w + biv.w);
    ((uint2*)(g_xnh + row * E_))[tid] = o;
}

// LayerNorm: in fp16 (g_attnh) -> out fp16 (g_nattnh)
__global__ __launch_bounds__(256) void ln_attn_kernel(const float* __restrict__ sc,
                                                      const float* __restrict__ bi) {
    __shared__ float red[16];
    const size_t row = blockIdx.x;
    const int tid = threadIdx.x;
    const uint2 u = ((const uint2*)(g_attnh + row * E_))[tid];
    const float2 f0 = h2unpack(u.x), f1 = h2unpack(u.y);
    const float4 v = {f0.x, f0.y, f1.x, f1.y};

    float s  = v.x + v.y + v.z + v.w;
    float sq = v.x * v.x + v.y * v.y + v.z * v.z + v.w * v.w;
#pragma unroll
    for (int o = 16; o > 0; o >>= 1) {
        s  += __shfl_xor_sync(0xFFFFFFFFu, s, o);
        sq += __shfl_xor_sync(0xFFFFFFFFu, sq, o);
    }
    const int warp = tid >> 5, lane = tid & 31;
    if (lane == 0) { red[warp] = s; red[8 + warp] = sq; }
    __syncthreads();
    if (tid < 32) {
        float ss = (lane < 8) ? red[lane] : 0.0f;
        float qq = (lane < 8) ? red[8 + lane] : 0.0f;
#pragma unroll
        for (int o = 4; o > 0; o >>= 1) {
            ss += __shfl_xor_sync(0xFFFFFFFFu, ss, o);
            qq += __shfl_xor_sync(0xFFFFFFFFu, qq, o);
        }
        if (lane == 0) { red[0] = ss; red[1] = qq; }
    }
    __syncthreads();
    const float mean = red[0] * (1.0f / (float)E_);
    const float var  = red[1] * (1.0f / (float)E_) - mean * mean;
    const float r    = rsqrtf(var + 1e-6f);

    const float4 scv = ((const float4*)sc)[tid];
    const float4 biv = ((const float4*)bi)[tid];
    uint2 o;
    o.x = h2pack((v.x - mean) * r * scv.x + biv.x, (v.y - mean) * r * scv.y + biv.y);
    o.y = h2pack((v.z - mean) * r * scv.z + biv.z, (v.w - mean) * r * scv.w + biv.w);
    ((uint2*)(g_nattnh + row * E_))[tid] = o;
}

// ---------------------------------------------------------------------------
// fp16 GEMM geometry: 128x128 tile, BK=32 halves (16 u32 words/row),
// 256 threads (8 warps 2x4), warp 64x32.  Row stride 20 words (%32==4,
// conflict-free for (g-row, tg-word) fragment pattern).
// ---------------------------------------------------------------------------
#define WSTRIDE 20
#define TSTG (128 * WSTRIDE)
#define G1_SMEM ((4 * TSTG + 4 * TSTG) * 4)
#define G2_SMEM ((2 * TSTG + 4 * TSTG) * 4)

// GEMM1: g_uvqkh[8192][4096] = g_xnh @ w1 + beta ; also writes fp32 V to g_vf
__global__ __launch_bounds__(256) void gemm_uvqk_fp16(const float* __restrict__ beta) {
    constexpr int K = E_, N = UVQK_;
    extern __shared__ uint32_t dsm[];
    uint32_t* As = dsm;
    uint32_t* Bs = dsm + 4 * TSTG;

    const int tid = threadIdx.x;
    const int row0 = blockIdx.y * 128, col0 = blockIdx.x * 128;
    const int wid = tid >> 5, lane = tid & 31;
    const int g = lane >> 2, tg = lane & 3;
    const int wm = wid >> 2, wn = wid & 3;
    const uint32_t asb = s2u(As), bsb = s2u(Bs);
    const bool is_vseg = (blockIdx.x >= 8 && blockIdx.x < 16);

    auto docopy = [&](int k0, int buf) {
#pragma unroll
        for (int p = 0; p < 2; p++) {
            const int id = tid + 256 * p;
            const int r = id >> 2, q = id & 3;
            cpa16(asb + (buf * TSTG + r * WSTRIDE + q * 4) * 4,
                  &g_xnh[(size_t)(row0 + r) * K + k0 + q * 8]);
        }
#pragma unroll
        for (int p = 0; p < 2; p++) {
            const int id = tid + 256 * p;
            const int r = id >> 2, q = id & 3;
            cpa16(bsb + (buf * TSTG + r * WSTRIDE + q * 4) * 4,
                  &g_w1h[(size_t)(col0 + r) * K + k0 + q * 8]);
        }
    };

    float acc[4][4][4];
#pragma unroll
    for (int i = 0; i < 4; i++)
#pragma unroll
        for (int j = 0; j < 4; j++)
#pragma unroll
            for (int r = 0; r < 4; r++) acc[i][j][r] = 0.0f;

    docopy(0, 0);  CP_COMMIT();
    docopy(32, 1); CP_COMMIT();
    docopy(64, 2); CP_COMMIT();

    for (int it = 0; it < K / 32; it++) {
        const int buf = it & 3;
        CP_WAIT(2);
        __syncthreads();
        if ((it + 3) * 32 < K) docopy((it + 3) * 32, (it + 3) & 3);
        CP_COMMIT();
#pragma unroll
        for (int kw = 0; kw < 16; kw += 8) {   // 2 x (k=16) steps
            uint32_t a[4][4], b[4][2];
#pragma unroll
            for (int mi = 0; mi < 4; mi++) {
                const int ab = buf * TSTG + (wm * 64 + mi * 16 + g) * WSTRIDE + kw + tg;
                a[mi][0] = As[ab];
                a[mi][1] = As[ab + 8 * WSTRIDE];
                a[mi][2] = As[ab + 4];
                a[mi][3] = As[ab + 8 * WSTRIDE + 4];
            }
#pragma unroll
            for (int ni = 0; ni < 4; ni++) {
                const int bb = buf * TSTG + (wn * 32 + ni * 8 + g) * WSTRIDE + kw + tg;
                b[ni][0] = Bs[bb];
                b[ni][1] = Bs[bb + 4];
            }
#pragma unroll
            for (int mi = 0; mi < 4; mi++)
#pragma unroll
                for (int ni = 0; ni < 4; ni++)
                    mma16(acc[mi][ni], a[mi], b[ni]);
        }
    }

#pragma unroll
    for (int mi = 0; mi < 4; mi++) {
        const int r1 = row0 + wm * 64 + mi * 16 + g;
#pragma unroll
        for (int ni = 0; ni < 4; ni++) {
            const int c = col0 + wn * 32 + ni * 8 + 2 * tg;
            const float2 bb = *(const float2*)&beta[c];
            const float v00 = acc[mi][ni][0] + bb.x, v01 = acc[mi][ni][1] + bb.y;
            const float v10 = acc[mi][ni][2] + bb.x, v11 = acc[mi][ni][3] + bb.y;
            *(uint32_t*)&g_uvqkh[(size_t)r1 * N + c] = h2pack(v00, v01);
            *(uint32_t*)&g_uvqkh[(size_t)(r1 + 8) * N + c] = h2pack(v10, v11);
            if (is_vseg) {
                float2 f0 = {v00, v01}, f1 = {v10, v11};
                *(float2*)&g_vf[(size_t)r1 * E_ + (c - 1024)] = f0;
                *(float2*)&g_vf[(size_t)(r1 + 8) * E_ + (c - 1024)] = f1;
            }
        }
    }
}

// GEMM2: out = x + A[8192][3072] @ w2 ; A assembled fp16, B 4-stage cp.async
__global__ __launch_bounds__(256) void gemm_out_fp16(const float* __restrict__ x,
                                                     float* __restrict__ out) {
    constexpr int K = 3072, N = E_;
    extern __shared__ uint32_t dsm2[];
    uint32_t* As = dsm2;               // 2 bufs
    uint32_t* Bs = dsm2 + 2 * TSTG;    // 4 stages
    const uint32_t bsb = s2u(Bs);

    const int tid = threadIdx.x;
    const int row0 = blockIdx.y * 128, col0 = blockIdx.x * 128;
    const int wid = tid >> 5, lane = tid & 31;
    const int g = lane >> 2, tg = lane & 3;
    const int wm = wid >> 2, wn = wid & 3;

    auto copyB = [&](int k0, int buf) {
#pragma unroll
        for (int p = 0; p < 2; p++) {
            const int id = tid + 256 * p;
            const int r = id >> 2, q = id & 3;
            cpa16(bsb + (buf * TSTG + r * WSTRIDE + q * 4) * 4,
                  &g_w2h[(size_t)(col0 + r) * K + k0 + q * 8]);
        }
    };
    auto loadA = [&](int k0, int p) -> uint4 {
        const int id = tid + 256 * p;
        const int r = id >> 2, q = id & 3;
        const int m = row0 + r;
        const int kg = k0 + q * 8;
        const int seg = kg >> 10, kloc = kg & 1023;
        uint4 av;
        if (seg == 0) {
            const uint4 t = *(const uint4*)&g_uvqkh[(size_t)m * UVQK_ + kloc];
            av.x = silu_h2(t.x); av.y = silu_h2(t.y);
            av.z = silu_h2(t.z); av.w = silu_h2(t.w);
        } else if (seg == 1) {
            av = *(const uint4*)&g_attnh[(size_t)m * E_ + kloc];
        } else {
            const uint4 t = *(const uint4*)&g_uvqkh[(size_t)m * UVQK_ + kloc];
            const uint4 nn = *(const uint4*)&g_nattnh[(size_t)m * E_ + kloc];
            float2 u0 = h2unpack(t.x), n0 = h2unpack(nn.x);
            float2 u1 = h2unpack(t.y), n1 = h2unpack(nn.y);
            float2 u2 = h2unpack(t.z), n2 = h2unpack(nn.z);
            float2 u3 = h2unpack(t.w), n3 = h2unpack(nn.w);
            av.x = h2pack(silu_f(u0.x) * n0.x, silu_f(u0.y) * n0.y);
            av.y = h2pack(silu_f(u1.x) * n1.x, silu_f(u1.y) * n1.y);
            av.z = h2pack(silu_f(u2.x) * n2.x, silu_f(u2.y) * n2.y);
            av.w = h2pack(silu_f(u3.x) * n3.x, silu_f(u3.y) * n3.y);
        }
        return av;
    };

    float acc[4][4][4];
#pragma unroll
    for (int i = 0; i < 4; i++)
#pragma unroll
        for (int j = 0; j < 4; j++)
#pragma unroll
            for (int r = 0; r < 4; r++) acc[i][j][r] = 0.0f;

    uint4 ra[2];
#pragma unroll
    for (int p = 0; p < 2; p++) ra[p] = loadA(0, p);
    copyB(0, 0);  CP_COMMIT();
    copyB(32, 1); CP_COMMIT();
    copyB(64, 2); CP_COMMIT();

    for (int it = 0; it < K / 32; it++) {
        const int bufB = it & 3, bufA = it & 1;
#pragma unroll
        for (int p = 0; p < 2; p++) {
            const int id = tid + 256 * p;
            const int r = id >> 2, q = id & 3;
            *(uint4*)&As[bufA * TSTG + r * WSTRIDE + q * 4] = ra[p];
        }
        if ((it + 1) * 32 < K) {
#pragma unroll
            for (int p = 0; p < 2; p++) ra[p] = loadA((it + 1) * 32, p);
        }
        CP_WAIT(2);
        __syncthreads();
        if ((it + 3) * 32 < K) copyB((it + 3) * 32, (it + 3) & 3);
        CP_COMMIT();
#pragma unroll
        for (int kw = 0; kw < 16; kw += 8) {
            uint32_t a[4][4], b[4][2];
#pragma unroll
            for (int mi = 0; mi < 4; mi++) {
                const int ab = bufA * TSTG + (wm * 64 + mi * 16 + g) * WSTRIDE + kw + tg;
                a[mi][0] = As[ab];
                a[mi][1] = As[ab + 8 * WSTRIDE];
                a[mi][2] = As[ab + 4];
                a[mi][3] = As[ab + 8 * WSTRIDE + 4];
            }
#pragma unroll
            for (int ni = 0; ni < 4; ni++) {
                const int bb = bufB * TSTG + (wn * 32 + ni * 8 + g) * WSTRIDE + kw + tg;
                b[ni][0] = Bs[bb];
                b[ni][1] = Bs[bb + 4];
            }
#pragma unroll
            for (int mi = 0; mi < 4; mi++)
#pragma unroll
                for (int ni = 0; ni < 4; ni++)
                    mma16(acc[mi][ni], a[mi], b[ni]);
        }
        __syncthreads();   // A-buf reuse distance 2
    }

#pragma unroll
    for (int mi = 0; mi < 4; mi++) {
        const int r1 = row0 + wm * 64 + mi * 16 + g;
#pragma unroll
        for (int ni = 0; ni < 4; ni++) {
            const int c = col0 + wn * 32 + ni * 8 + 2 * tg;
            const float2 x0 = *(const float2*)&x[(size_t)r1 * N + c];
            const float2 x1 = *(const float2*)&x[(size_t)(r1 + 8) * N + c];
            float2 o0 = {acc[mi][ni][0] + x0.x, acc[mi][ni][1] + x0.y};
            float2 o1 = {acc[mi][ni][2] + x1.x, acc[mi][ni][3] + x1.y};
            *(float2*)&out[(size_t)r1 * N + c] = o0;
            *(float2*)&out[(size_t)(r1 + 8) * N + c] = o1;
        }
    }
}

// ---------------------------------------------------------------------------
// Attention: 128 q-rows/CTA, 512 threads (16 warps 4x4).
// Stage1 fp16: S[128,64] = Q K^T  (warp 32x16), Q/K halves, stride 68 words.
// Stage2 tf32: O[128,128] += P V  (warp 32x32), P fp32 (68), V fp32 (132).
// K double-buffered; V single-buffered, overlapped with next stage1.
// ---------------------------------------------------------------------------
#define QW   68     // words per 128-half row (64 + pad 4; %32==4 conflict-free)
#define VPAD 132
#define PPAD 68
#define AT_Q (128 * QW)
#define AT_K (64 * QW)
#define AT_V (64 * VPAD)
#define ATTN_WORDS (AT_Q + 2 * AT_K + AT_V + 128 * PPAD)
#define ATTN_SMEM_BYTES (ATTN_WORDS * 4)

__global__ __launch_bounds__(512) void attn_tc(const int* __restrict__ num_targets) {
    extern __shared__ uint32_t smw[];
    uint32_t* qs = smw;                   // Q halves: 128 x 68 words
    uint32_t* kb = qs + AT_Q;             // K halves: 2 x 64 x 68
    uint32_t* vs = kb + 2 * AT_K;         // V fp32:   64 x 132
    float*    ps = (float*)(vs + AT_V);   // P fp32:   128 x 68

    const int tid = threadIdx.x;
    const int wid = tid >> 5, lane = tid & 31;
    const int g = lane >> 2, tg = lane & 3;
    const int wm = wid >> 2, wn = wid & 3;

    const int b = blockIdx.z, h = blockIdx.y;
    const int qt = (gridDim.x - 1) - blockIdx.x;   // heavy tiles first
    const int q0 = qt * 128;
    const int limit = S_ - num_targets[b];
    const __half* baseh = g_uvqkh + (size_t)b * S_ * UVQK_;
    const uint32_t qsb = s2u(qs), kbb = s2u(kb), vsb = s2u(vs);

    auto loadK = [&](int t, int buf) {
        const int k0 = t * 64;
#pragma unroll
        for (int p = 0; p < 2; p++) {
            const int id = tid + 512 * p;
            const int r = id >> 4, c = id & 15;
            cpa16(kbb + (buf * AT_K + r * QW + c * 4) * 4,
                  &baseh[(size_t)(k0 + r) * UVQK_ + 3072 + h * D_ + c * 8]);
        }
    };
    auto loadV = [&](int t) {
        const int k0 = t * 64;
#pragma unroll
        for (int p = 0; p < 4; p++) {
            const int id = tid + 512 * p;
            const int r = id >> 5, c = id & 31;
            cpa16(vsb + (r * VPAD + c * 4) * 4,
                  &g_vf[(size_t)(b * S_ + k0 + r) * E_ + h * D_ + c * 4]);
        }
    };

    // g0 = {Q, K0, V0}; g1 = {K1}
#pragma unroll
    for (int p = 0; p < 4; p++) {
        const int id = tid + 512 * p;
        const int r = id >> 4, c = id & 15;
        cpa16(qsb + (r * QW + c * 4) * 4,
              &baseh[(size_t)(q0 + r) * UVQK_ + 2048 + h * D_ + c * 8]);
    }
    const int ntile = 2 * qt + 2;
    loadK(0, 0);
    loadV(0);
    CP_COMMIT();
    if (ntile > 1) loadK(1, 1);
    CP_COMMIT();

    float oacc[2][4][4];
#pragma unroll
    for (int i = 0; i < 2; i++)
#pragma unroll
        for (int j = 0; j < 4; j++)
#pragma unroll
            for (int r = 0; r < 4; r++) oacc[i][j][r] = 0.0f;

    for (int t = 0; t < ntile; t++) {
        const int k0 = t * 64;
        const uint32_t* ks = kb + (t & 1) * AT_K;

        CP_WAIT(1);        // drains g_{2t} (V(t), K(t)); K(t+1) in flight
        __syncthreads();

        // ----- Stage 1 (fp16): S = Q @ K^T, warp tile 32m x 16n -----
        float sacc[2][2][4];
#pragma unroll
        for (int i = 0; i < 2; i++)
#pragma unroll
            for (int j = 0; j < 2; j++)
#pragma unroll
                for (int r = 0; r < 4; r++) sacc[i][j][r] = 0.0f;

#pragma unroll
        for (int kw = 0; kw < 64; kw += 8) {   // 8 k-steps of 16 halves
            uint32_t a[2][4], bf[2][2];
#pragma unroll
            for (int mi = 0; mi < 2; mi++) {
                const int ab = (wm * 32 + mi * 16 + g) * QW + kw + tg;
                a[mi][0] = qs[ab];
                a[mi][1] = qs[ab + 8 * QW];
                a[mi][2] = qs[ab + 4];
                a[mi][3] = qs[ab + 8 * QW + 4];
            }
#pragma unroll
            for (int ni = 0; ni < 2; ni++) {
                const int bb = (wn * 16 + ni * 8 + g) * QW + kw + tg;
                bf[ni][0] = ks[bb];
                bf[ni][1] = ks[bb + 4];
            }
#pragma unroll
            for (int mi = 0; mi < 2; mi++)
#pragma unroll
                for (int ni = 0; ni < 2; ni++)
                    mma16(sacc[mi][ni], a[mi], bf[ni]);
        }

        // silu + mask + rounded P store (fp32)
#pragma unroll
        for (int mi = 0; mi < 2; mi++) {
            const int qr = wm * 32 + mi * 16 + g;
            const int qg0 = q0 + qr, qg1 = qg0 + 8;
            const int iq0 = min(qg0, limit), iq1 = min(qg1, limit);
#pragma unroll
            for (int ni = 0; ni < 2; ni++) {
                const int cc = wn * 16 + ni * 8 + 2 * tg;
                const int kg0 = k0 + cc, kg1 = kg0 + 1;
                const int ik0 = min(kg0, limit), ik1 = min(kg1, limit);

                float p00 = ((qg0 == kg0) || (iq0 > ik0)) ? rndf(silu_f(sacc[mi][ni][0] * ALPHA_F) * INV_S_F) : 0.0f;
                float p01 = ((qg0 == kg1) || (iq0 > ik1)) ? rndf(silu_f(sacc[mi][ni][1] * ALPHA_F) * INV_S_F) : 0.0f;
                float p10 = ((qg1 == kg0) || (iq1 > ik0)) ? rndf(silu_f(sacc[mi][ni][2] * ALPHA_F) * INV_S_F) : 0.0f;
                float p11 = ((qg1 == kg1) || (iq1 > ik1)) ? rndf(silu_f(sacc[mi][ni][3] * ALPHA_F) * INV_S_F) : 0.0f;

                float2 u0 = {p00, p01};
                float2 u1 = {p10, p11};
                *(float2*)&ps[qr * PPAD + cc] = u0;
                *(float2*)&ps[(qr + 8) * PPAD + cc] = u1;
            }
        }
        __syncthreads();

        // ----- Stage 2 (tf32): O += P @ V, warp tile 32m x 32n -----
        const uint32_t* psw = (const uint32_t*)ps;
#pragma unroll
        for (int kc = 0; kc < 64; kc += 8) {
            uint32_t a[2][4], bf[4][2];
#pragma unroll
            for (int mi = 0; mi < 2; mi++) {
                const int ab = (wm * 32 + mi * 16 + g) * PPAD + kc + tg;
                a[mi][0] = psw[ab];
                a[mi][1] = psw[ab + 8 * PPAD];
                a[mi][2] = psw[ab + 4];
                a[mi][3] = psw[ab + 8 * PPAD + 4];
            }
#pragma unroll
            for (int ni = 0; ni < 4; ni++) {
                const int bb = (kc + tg) * VPAD + wn * 32 + ni * 8 + g;
                bf[ni][0] = vs[bb];
                bf[ni][1] = vs[bb + 4 * VPAD];
            }
#pragma unroll
            for (int mi = 0; mi < 2; mi++)
#pragma unroll
                for (int ni = 0; ni < 4; ni++)
                    mma8(oacc[mi][ni], a[mi], bf[ni]);
        }
        __syncthreads();   // all stage2 V reads done

        if (t + 1 < ntile) loadV(t + 1);
        CP_COMMIT();
        if (t + 2 < ntile) loadK(t + 2, t & 1);
        CP_COMMIT();
    }

    // Epilogue: fp16 attn output
#pragma unroll
    for (int mi = 0; mi < 2; mi++) {
        const int r1 = q0 + wm * 32 + mi * 16 + g;
#pragma unroll
        for (int ni = 0; ni < 4; ni++) {
            const int c = h * D_ + wn * 32 + ni * 8 + 2 * tg;
            *(uint32_t*)&g_attnh[(size_t)(b * S_ + r1) * E_ + c] =
                h2pack(oacc[mi][ni][0], oacc[mi][ni][1]);
            *(uint32_t*)&g_attnh[(size_t)(b * S_ + r1 + 8) * E_ + c] =
                h2pack(oacc[mi][ni][2], oacc[mi][ni][3]);
        }
    }
}

// ---------------------------------------------------------------------------
// Launch
// ---------------------------------------------------------------------------
extern "C" void kernel_launch(void* const* d_in, const int* in_sizes, int n_in,
                              void* d_out, int out_size) {
    const float* x        = (const float*)d_in[0];
    const int*   ntg      = (const int*)d_in[1];
    const float* uvqk_w   = (const float*)d_in[2];
    const float* uvqk_b   = (const float*)d_in[3];
    const float* out_w    = (const float*)d_in[4];
    const float* in_scale = (const float*)d_in[5];
    const float* in_bias  = (const float*)d_in[6];
    const float* out_scale= (const float*)d_in[7];
    const float* out_bias = (const float*)d_in[8];
    float* out = (float*)d_out;

    (void)in_sizes; (void)n_in; (void)out_size;

    static bool attr_set = false;
    if (!attr_set) {
        cudaFuncSetAttribute(attn_tc, cudaFuncAttributeMaxDynamicSharedMemorySize,
                             ATTN_SMEM_BYTES);
        cudaFuncSetAttribute(gemm_uvqk_fp16, cudaFuncAttributeMaxDynamicSharedMemorySize,
                             G1_SMEM);
        cudaFuncSetAttribute(gemm_out_fp16, cudaFuncAttributeMaxDynamicSharedMemorySize,
                             G2_SMEM);
        attr_set = true;
    }

    __half* w1h_ptr; cudaGetSymbolAddress((void**)&w1h_ptr, g_w1h);
    __half* w2h_ptr; cudaGetSymbolAddress((void**)&w2h_ptr, g_w2h);

    // weight transpose+halve: w1 [1024][4096] -> [4096][1024]; w2 [3072][1024] -> [1024][3072]
    transpose_half<<<dim3(E_ / 32, UVQK_ / 32), dim3(32, 8)>>>(uvqk_w, w1h_ptr, E_, UVQK_);
    transpose_half<<<dim3(3072 / 32, E_ / 32), dim3(32, 8)>>>(out_w, w2h_ptr, 3072, E_);

    ln_in_kernel<<<MTOT, 256>>>(x, in_scale, in_bias);
    gemm_uvqk_fp16<<<dim3(UVQK_ / 128, MTOT / 128), 256, G1_SMEM>>>(uvqk_b);
    attn_tc<<<dim3(S_ / 128, H_, B_), 512, ATTN_SMEM_BYTES>>>(ntg);
    ln_attn_kernel<<<MTOT, 256>>>(out_scale, out_bias);
    gemm_out_fp16<<<dim3(E_ / 128, MTOT / 128), 256, G2_SMEM>>>(x, out);
}

// round 10
// speedup vs baseline: 1.8486x; 1.2372x over previous
#include <cuda_runtime.h>
#include <cuda_fp16.h>
#include <math.h>
#include <stdint.h>

#define B_    4
#define S_    2048
#define E_    1024
#define H_    8
#define D_    128
#define UVQK_ 4096
#define MTOT  (B_ * S_)

#define ALPHA_F 0.08838834764831845f
#define INV_S_F (1.0f / 2048.0f)

// ---------------------------------------------------------------------------
// Scratch (fp16 operands everywhere)
// ---------------------------------------------------------------------------
__device__ __half g_xnh[(size_t)MTOT * E_];
__device__ __half g_uvqkh[(size_t)MTOT * UVQK_];
__device__ __half g_attnh[(size_t)MTOT * E_];
__device__ __half g_nattnh[(size_t)MTOT * E_];
__device__ __half g_w1h[(size_t)UVQK_ * E_];   // [n=4096][k=1024]
__device__ __half g_w2h[(size_t)E_ * 3072];    // [n=1024][k=3072]

__device__ __forceinline__ float silu_f(float v) {
    return v / (1.0f + __expf(-v));
}
// fp16 m16n8k16, fp32 accumulate
__device__ __forceinline__ void mma16(float* c, const uint32_t* a, const uint32_t* b) {
    asm volatile(
        "mma.sync.aligned.m16n8k16.row.col.f32.f16.f16.f32 "
        "{%0,%1,%2,%3}, {%4,%5,%6,%7}, {%8,%9}, {%0,%1,%2,%3};"
        : "+f"(c[0]), "+f"(c[1]), "+f"(c[2]), "+f"(c[3])
        : "r"(a[0]), "r"(a[1]), "r"(a[2]), "r"(a[3]), "r"(b[0]), "r"(b[1]));
}
__device__ __forceinline__ void ldsm4(uint32_t* r, uint32_t addr) {
    asm volatile("ldmatrix.sync.aligned.m8n8.x4.shared.b16 {%0,%1,%2,%3}, [%4];"
        : "=r"(r[0]), "=r"(r[1]), "=r"(r[2]), "=r"(r[3]) : "r"(addr));
}
__device__ __forceinline__ void ldsm4t(uint32_t* r, uint32_t addr) {
    asm volatile("ldmatrix.sync.aligned.m8n8.x4.trans.shared.b16 {%0,%1,%2,%3}, [%4];"
        : "=r"(r[0]), "=r"(r[1]), "=r"(r[2]), "=r"(r[3]) : "r"(addr));
}
__device__ __forceinline__ uint32_t s2u(const void* p) {
    return (uint32_t)__cvta_generic_to_shared(p);
}
__device__ __forceinline__ void cpa16(uint32_t dst, const void* src) {
    asm volatile("cp.async.cg.shared.global [%0], [%1], 16;" :: "r"(dst), "l"(src));
}
#define CP_COMMIT() asm volatile("cp.async.commit_group;")
#define CP_WAIT(N)  asm volatile("cp.async.wait_group %0;" :: "n"(N))

__device__ __forceinline__ uint32_t h2pack(float a, float b) {
    __half2 h = __float22half2_rn(make_float2(a, b));
    return *(uint32_t*)&h;
}
__device__ __forceinline__ float2 h2unpack(uint32_t u) {
    return __half22float2(*(__half2*)&u);
}
__device__ __forceinline__ uint32_t silu_h2(uint32_t u) {
    float2 f = h2unpack(u);
    return h2pack(silu_f(f.x), silu_f(f.y));
}

// ---------------------------------------------------------------------------
// Weight prep: transpose [K][N] fp32 -> [N][K] fp16
// ---------------------------------------------------------------------------
__global__ __launch_bounds__(256) void transpose_half(const float* __restrict__ src,
                                                      __half* __restrict__ dst,
                                                      int K, int N) {
    __shared__ float t[32][33];
    const int k0 = blockIdx.x * 32, n0 = blockIdx.y * 32;
    const int tx = threadIdx.x, ty = threadIdx.y;  // 32 x 8
#pragma unroll
    for (int j = 0; j < 4; j++)
        t[ty + 8 * j][tx] = src[(size_t)(k0 + ty + 8 * j) * N + n0 + tx];
    __syncthreads();
#pragma unroll
    for (int j = 0; j < 4; j++)
        dst[(size_t)(n0 + ty + 8 * j) * K + k0 + tx] = __float2half(t[tx][ty + 8 * j]);
}

// ---------------------------------------------------------------------------
// LayerNorms
// ---------------------------------------------------------------------------
__global__ __launch_bounds__(256) void ln_in_kernel(const float* __restrict__ x,
                                                    const float* __restrict__ sc,
                                                    const float* __restrict__ bi) {
    __shared__ float red[16];
    const size_t row = blockIdx.x;
    const int tid = threadIdx.x;
    const float4 v = ((const float4*)(x + row * E_))[tid];

    float s  = v.x + v.y + v.z + v.w;
    float sq = v.x * v.x + v.y * v.y + v.z * v.z + v.w * v.w;
#pragma unroll
    for (int o = 16; o > 0; o >>= 1) {
        s  += __shfl_xor_sync(0xFFFFFFFFu, s, o);
        sq += __shfl_xor_sync(0xFFFFFFFFu, sq, o);
    }
    const int warp = tid >> 5, lane = tid & 31;
    if (lane == 0) { red[warp] = s; red[8 + warp] = sq; }
    __syncthreads();
    if (tid < 32) {
        float ss = (lane < 8) ? red[lane] : 0.0f;
        float qq = (lane < 8) ? red[8 + lane] : 0.0f;
#pragma unroll
        for (int o = 4; o > 0; o >>= 1) {
            ss += __shfl_xor_sync(0xFFFFFFFFu, ss, o);
            qq += __shfl_xor_sync(0xFFFFFFFFu, qq, o);
        }
        if (lane == 0) { red[0] = ss; red[1] = qq; }
    }
    __syncthreads();
    const float mean = red[0] * (1.0f / (float)E_);
    const float var  = red[1] * (1.0f / (float)E_) - mean * mean;
    const float r    = rsqrtf(var + 1e-6f);

    const float4 scv = ((const float4*)sc)[tid];
    const float4 biv = ((const float4*)bi)[tid];
    uint2 o;
    o.x = h2pack((v.x - mean) * r * scv.x + biv.x, (v.y - mean) * r * scv.y + biv.y);
    o.y = h2pack((v.z - mean) * r * scv.z + biv.z, (v.w - mean) * r * scv.w + biv.w);
    ((uint2*)(g_xnh + row * E_))[tid] = o;
}

__global__ __launch_bounds__(256) void ln_attn_kernel(const float* __restrict__ sc,
                                                      const float* __restrict__ bi) {
    __shared__ float red[16];
    const size_t row = blockIdx.x;
    const int tid = threadIdx.x;
    const uint2 u = ((const uint2*)(g_attnh + row * E_))[tid];
    const float2 f0 = h2unpack(u.x), f1 = h2unpack(u.y);
    const float4 v = {f0.x, f0.y, f1.x, f1.y};

    float s  = v.x + v.y + v.z + v.w;
    float sq = v.x * v.x + v.y * v.y + v.z * v.z + v.w * v.w;
#pragma unroll
    for (int o = 16; o > 0; o >>= 1) {
        s  += __shfl_xor_sync(0xFFFFFFFFu, s, o);
        sq += __shfl_xor_sync(0xFFFFFFFFu, sq, o);
    }
    const int warp = tid >> 5, lane = tid & 31;
    if (lane == 0) { red[warp] = s; red[8 + warp] = sq; }
    __syncthreads();
    if (tid < 32) {
        float ss = (lane < 8) ? red[lane] : 0.0f;
        float qq = (lane < 8) ? red[8 + lane] : 0.0f;
#pragma unroll
        for (int o = 4; o > 0; o >>= 1) {
            ss += __shfl_xor_sync(0xFFFFFFFFu, ss, o);
            qq += __shfl_xor_sync(0xFFFFFFFFu, qq, o);
        }
        if (lane == 0) { red[0] = ss; red[1] = qq; }
    }
    __syncthreads();
    const float mean = red[0] * (1.0f / (float)E_);
    const float var  = red[1] * (1.0f / (float)E_) - mean * mean;
    const float r    = rsqrtf(var + 1e-6f);

    const float4 scv = ((const float4*)sc)[tid];
    const float4 biv = ((const float4*)bi)[tid];
    uint2 o;
    o.x = h2pack((v.x - mean) * r * scv.x + biv.x, (v.y - mean) * r * scv.y + biv.y);
    o.y = h2pack((v.z - mean) * r * scv.z + biv.z, (v.w - mean) * r * scv.w + biv.w);
    ((uint2*)(g_nattnh + row * E_))[tid] = o;
}

// ---------------------------------------------------------------------------
// fp16 GEMM: 128x128, BK=32 halves (16 words), 256 thr (8 warps 2x4),
// warp 64x32, ldmatrix fragment loads. WSTRIDE=20 (%32==4 -> conflict-free).
// ---------------------------------------------------------------------------
#define WSTRIDE 20
#define TSTG (128 * WSTRIDE)
#define G1_SMEM ((4 * TSTG + 4 * TSTG) * 4)
#define G2_SMEM ((2 * TSTG + 4 * TSTG) * 4)

// GEMM1: g_uvqkh = g_xnh @ w1 + beta
__global__ __launch_bounds__(256) void gemm_uvqk_fp16(const float* __restrict__ beta) {
    constexpr int K = E_, N = UVQK_;
    extern __shared__ uint32_t dsm[];
    uint32_t* As = dsm;
    uint32_t* Bs = dsm + 4 * TSTG;

    const int tid = threadIdx.x;
    const int row0 = blockIdx.y * 128, col0 = blockIdx.x * 128;
    const int wid = tid >> 5, lane = tid & 31;
    const int g = lane >> 2, tg = lane & 3;
    const int wm = wid >> 2, wn = wid & 3;
    const uint32_t asb = s2u(As), bsb = s2u(Bs);

    // ldmatrix per-lane bases (word offsets)
    const int a_base = (wm * 64 + (lane & 15)) * WSTRIDE + ((lane & 16) >> 2);
    const int b_base = (wn * 32 + (lane & 7) + ((lane & 16) >> 1)) * WSTRIDE + ((lane & 8) >> 1);

    auto docopy = [&](int k0, int buf) {
#pragma unroll
        for (int p = 0; p < 2; p++) {
            const int id = tid + 256 * p;
            const int r = id >> 2, q = id & 3;
            cpa16(asb + (buf * TSTG + r * WSTRIDE + q * 4) * 4,
                  &g_xnh[(size_t)(row0 + r) * K + k0 + q * 8]);
        }
#pragma unroll
        for (int p = 0; p < 2; p++) {
            const int id = tid + 256 * p;
            const int r = id >> 2, q = id & 3;
            cpa16(bsb + (buf * TSTG + r * WSTRIDE + q * 4) * 4,
                  &g_w1h[(size_t)(col0 + r) * K + k0 + q * 8]);
        }
    };

    float acc[4][4][4];
#pragma unroll
    for (int i = 0; i < 4; i++)
#pragma unroll
        for (int j = 0; j < 4; j++)
#pragma unroll
            for (int r = 0; r < 4; r++) acc[i][j][r] = 0.0f;

    docopy(0, 0);  CP_COMMIT();
    docopy(32, 1); CP_COMMIT();
    docopy(64, 2); CP_COMMIT();

    for (int it = 0; it < K / 32; it++) {
        const int buf = it & 3;
        CP_WAIT(2);
        __syncthreads();
        if ((it + 3) * 32 < K) docopy((it + 3) * 32, (it + 3) & 3);
        CP_COMMIT();
#pragma unroll
        for (int kw = 0; kw < 16; kw += 8) {
            uint32_t a[4][4], b[4][2];
#pragma unroll
            for (int mi = 0; mi < 4; mi++)
                ldsm4(a[mi], asb + (buf * TSTG + a_base + mi * 16 * WSTRIDE + kw) * 4);
#pragma unroll
            for (int np = 0; np < 2; np++) {
                uint32_t t[4];
                ldsm4(t, bsb + (buf * TSTG + b_base + np * 16 * WSTRIDE + kw) * 4);
                b[2 * np][0] = t[0]; b[2 * np][1] = t[1];
                b[2 * np + 1][0] = t[2]; b[2 * np + 1][1] = t[3];
            }
#pragma unroll
            for (int mi = 0; mi < 4; mi++)
#pragma unroll
                for (int ni = 0; ni < 4; ni++)
                    mma16(acc[mi][ni], a[mi], b[ni]);
        }
    }

#pragma unroll
    for (int mi = 0; mi < 4; mi++) {
        const int r1 = row0 + wm * 64 + mi * 16 + g;
#pragma unroll
        for (int ni = 0; ni < 4; ni++) {
            const int c = col0 + wn * 32 + ni * 8 + 2 * tg;
            const float2 bb = *(const float2*)&beta[c];
            *(uint32_t*)&g_uvqkh[(size_t)r1 * N + c] =
                h2pack(acc[mi][ni][0] + bb.x, acc[mi][ni][1] + bb.y);
            *(uint32_t*)&g_uvqkh[(size_t)(r1 + 8) * N + c] =
                h2pack(acc[mi][ni][2] + bb.x, acc[mi][ni][3] + bb.y);
        }
    }
}

// GEMM2: out = x + A[8192][3072] @ w2
__global__ __launch_bounds__(256) void gemm_out_fp16(const float* __restrict__ x,
                                                     float* __restrict__ out) {
    constexpr int K = 3072, N = E_;
    extern __shared__ uint32_t dsm2[];
    uint32_t* As = dsm2;               // 2 bufs
    uint32_t* Bs = dsm2 + 2 * TSTG;    // 4 stages
    const uint32_t asb = s2u(As), bsb = s2u(Bs);

    const int tid = threadIdx.x;
    const int row0 = blockIdx.y * 128, col0 = blockIdx.x * 128;
    const int wid = tid >> 5, lane = tid & 31;
    const int g = lane >> 2, tg = lane & 3;
    const int wm = wid >> 2, wn = wid & 3;

    const int a_base = (wm * 64 + (lane & 15)) * WSTRIDE + ((lane & 16) >> 2);
    const int b_base = (wn * 32 + (lane & 7) + ((lane & 16) >> 1)) * WSTRIDE + ((lane & 8) >> 1);

    auto copyB = [&](int k0, int buf) {
#pragma unroll
        for (int p = 0; p < 2; p++) {
            const int id = tid + 256 * p;
            const int r = id >> 2, q = id & 3;
            cpa16(bsb + (buf * TSTG + r * WSTRIDE + q * 4) * 4,
                  &g_w2h[(size_t)(col0 + r) * K + k0 + q * 8]);
        }
    };
    auto loadA = [&](int k0, int p) -> uint4 {
        const int id = tid + 256 * p;
        const int r = id >> 2, q = id & 3;
        const int m = row0 + r;
        const int kg = k0 + q * 8;
        const int seg = kg >> 10, kloc = kg & 1023;
        uint4 av;
        if (seg == 0) {
            const uint4 t = *(const uint4*)&g_uvqkh[(size_t)m * UVQK_ + kloc];
            av.x = silu_h2(t.x); av.y = silu_h2(t.y);
            av.z = silu_h2(t.z); av.w = silu_h2(t.w);
        } else if (seg == 1) {
            av = *(const uint4*)&g_attnh[(size_t)m * E_ + kloc];
        } else {
            const uint4 t = *(const uint4*)&g_uvqkh[(size_t)m * UVQK_ + kloc];
            const uint4 nn = *(const uint4*)&g_nattnh[(size_t)m * E_ + kloc];
            float2 u0 = h2unpack(t.x), n0 = h2unpack(nn.x);
            float2 u1 = h2unpack(t.y), n1 = h2unpack(nn.y);
            float2 u2 = h2unpack(t.z), n2 = h2unpack(nn.z);
            float2 u3 = h2unpack(t.w), n3 = h2unpack(nn.w);
            av.x = h2pack(silu_f(u0.x) * n0.x, silu_f(u0.y) * n0.y);
            av.y = h2pack(silu_f(u1.x) * n1.x, silu_f(u1.y) * n1.y);
            av.z = h2pack(silu_f(u2.x) * n2.x, silu_f(u2.y) * n2.y);
            av.w = h2pack(silu_f(u3.x) * n3.x, silu_f(u3.y) * n3.y);
        }
        return av;
    };

    float acc[4][4][4];
#pragma unroll
    for (int i = 0; i < 4; i++)
#pragma unroll
        for (int j = 0; j < 4; j++)
#pragma unroll
            for (int r = 0; r < 4; r++) acc[i][j][r] = 0.0f;

    uint4 ra[2];
#pragma unroll
    for (int p = 0; p < 2; p++) ra[p] = loadA(0, p);
    copyB(0, 0);  CP_COMMIT();
    copyB(32, 1); CP_COMMIT();
    copyB(64, 2); CP_COMMIT();

    for (int it = 0; it < K / 32; it++) {
        const int bufB = it & 3, bufA = it & 1;
#pragma unroll
        for (int p = 0; p < 2; p++) {
            const int id = tid + 256 * p;
            const int r = id >> 2, q = id & 3;
            *(uint4*)&As[bufA * TSTG + r * WSTRIDE + q * 4] = ra[p];
        }
        if ((it + 1) * 32 < K) {
#pragma unroll
            for (int p = 0; p < 2; p++) ra[p] = loadA((it + 1) * 32, p);
        }
        CP_WAIT(2);
        __syncthreads();
        if ((it + 3) * 32 < K) copyB((it + 3) * 32, (it + 3) & 3);
        CP_COMMIT();
#pragma unroll
        for (int kw = 0; kw < 16; kw += 8) {
            uint32_t a[4][4], b[4][2];
#pragma unroll
            for (int mi = 0; mi < 4; mi++)
                ldsm4(a[mi], asb + (bufA * TSTG + a_base + mi * 16 * WSTRIDE + kw) * 4);
#pragma unroll
            for (int np = 0; np < 2; np++) {
                uint32_t t[4];
                ldsm4(t, bsb + (bufB * TSTG + b_base + np * 16 * WSTRIDE + kw) * 4);
                b[2 * np][0] = t[0]; b[2 * np][1] = t[1];
                b[2 * np + 1][0] = t[2]; b[2 * np + 1][1] = t[3];
            }
#pragma unroll
            for (int mi = 0; mi < 4; mi++)
#pragma unroll
                for (int ni = 0; ni < 4; ni++)
                    mma16(acc[mi][ni], a[mi], b[ni]);
        }
        __syncthreads();   // A-buf reuse distance 2
    }

#pragma unroll
    for (int mi = 0; mi < 4; mi++) {
        const int r1 = row0 + wm * 64 + mi * 16 + g;
#pragma unroll
        for (int ni = 0; ni < 4; ni++) {
            const int c = col0 + wn * 32 + ni * 8 + 2 * tg;
            const float2 x0 = *(const float2*)&x[(size_t)r1 * N + c];
            const float2 x1 = *(const float2*)&x[(size_t)(r1 + 8) * N + c];
            float2 o0 = {acc[mi][ni][0] + x0.x, acc[mi][ni][1] + x0.y};
            float2 o1 = {acc[mi][ni][2] + x1.x, acc[mi][ni][3] + x1.y};
            *(float2*)&out[(size_t)r1 * N + c] = o0;
            *(float2*)&out[(size_t)(r1 + 8) * N + c] = o1;
        }
    }
}

// ---------------------------------------------------------------------------
// Attention: 128 q-rows/CTA, 512 thr (16 warps 4x4), ALL-fp16, ldmatrix.
// Deferred 1/S: P = silu(score*alpha) fp16, O scaled by 1/S at epilogue.
// Stage1: S[128,64] = Q K^T (warp 32x16); Stage2: O[128,128] += P V (warp 32x32)
// smem: Q 128x68, K 2x64x68, V 64x68, P 128x36 words = ~103KB -> 2 CTA/SM.
// ---------------------------------------------------------------------------
#define QW 68   // words per 128-half row (64 data + 4 pad; %32==4)
#define PW 36   // words per 64-half P row (32 data + 4 pad; %32==4)
#define AT_Q (128 * QW)
#define AT_K (64 * QW)
#define AT_V (64 * QW)
#define ATTN_WORDS (AT_Q + 2 * AT_K + AT_V + 128 * PW)
#define ATTN_SMEM_BYTES (ATTN_WORDS * 4)

__global__ __launch_bounds__(512, 2) void attn_tc(const int* __restrict__ num_targets) {
    extern __shared__ uint32_t smw[];
    uint32_t* qs  = smw;                 // Q: 128 x 68
    uint32_t* kb  = qs + AT_Q;           // K: 2 x 64 x 68
    uint32_t* vsh = kb + 2 * AT_K;       // V: 64 x 68
    uint32_t* psh = vsh + AT_V;          // P: 128 x 36 (fp16 pairs)

    const int tid = threadIdx.x;
    const int wid = tid >> 5, lane = tid & 31;
    const int g = lane >> 2, tg = lane & 3;
    const int wm = wid >> 2, wn = wid & 3;

    const int b = blockIdx.z, h = blockIdx.y;
    const int qt = (gridDim.x - 1) - blockIdx.x;   // heavy tiles first
    const int q0 = qt * 128;
    const int limit = S_ - num_targets[b];
    const __half* baseh = g_uvqkh + (size_t)b * S_ * UVQK_;
    const uint32_t qsb = s2u(qs), kbb = s2u(kb), vsb = s2u(vsh), psb = s2u(psh);

    // ldmatrix per-lane bases (word offsets)
    const int qa_base = (wm * 32 + (lane & 15)) * QW + ((lane & 16) >> 2);          // Q as A
    const int kb_base = (wn * 16 + (lane & 7) + ((lane & 16) >> 1)) * QW + ((lane & 8) >> 1); // K as B
    const int pa_base = (wm * 32 + (lane & 15)) * PW + ((lane & 16) >> 2);          // P as A
    const int vb_base = ((lane & 7) + (lane & 8)) * QW + wn * 16 + ((lane & 16) >> 2); // V as B (trans)

    auto loadK = [&](int t, int buf) {
        const int k0 = t * 64;
#pragma unroll
        for (int p = 0; p < 2; p++) {
            const int id = tid + 512 * p;
            const int r = id >> 4, c = id & 15;
            cpa16(kbb + (buf * AT_K + r * QW + c * 4) * 4,
                  &baseh[(size_t)(k0 + r) * UVQK_ + 3072 + h * D_ + c * 8]);
        }
    };
    auto loadV = [&](int t) {
        const int k0 = t * 64;
#pragma unroll
        for (int p = 0; p < 2; p++) {
            const int id = tid + 512 * p;
            const int r = id >> 4, c = id & 15;
            cpa16(vsb + (r * QW + c * 4) * 4,
                  &baseh[(size_t)(k0 + r) * UVQK_ + 1024 + h * D_ + c * 8]);
        }
    };

    // g0 = {Q, K0, V0}; g1 = {K1}
#pragma unroll
    for (int p = 0; p < 4; p++) {
        const int id = tid + 512 * p;
        const int r = id >> 4, c = id & 15;
        cpa16(qsb + (r * QW + c * 4) * 4,
              &baseh[(size_t)(q0 + r) * UVQK_ + 2048 + h * D_ + c * 8]);
    }
    const int ntile = 2 * qt + 2;
    loadK(0, 0);
    loadV(0);
    CP_COMMIT();
    if (ntile > 1) loadK(1, 1);
    CP_COMMIT();

    float oacc[2][4][4];
#pragma unroll
    for (int i = 0; i < 2; i++)
#pragma unroll
        for (int j = 0; j < 4; j++)
#pragma unroll
            for (int r = 0; r < 4; r++) oacc[i][j][r] = 0.0f;

    for (int t = 0; t < ntile; t++) {
        const int k0 = t * 64;
        const int kbuf = (t & 1) * AT_K;

        CP_WAIT(1);        // drains g_{2t} (V(t), K(t)); K(t+1) in flight
        __syncthreads();

        // ----- Stage 1 (fp16): S = Q @ K^T, warp tile 32m x 16n -----
        float sacc[2][2][4];
#pragma unroll
        for (int i = 0; i < 2; i++)
#pragma unroll
            for (int j = 0; j < 2; j++)
#pragma unroll
                for (int r = 0; r < 4; r++) sacc[i][j][r] = 0.0f;

#pragma unroll
        for (int kw = 0; kw < 64; kw += 8) {
            uint32_t a[2][4], bf[2][2];
#pragma unroll
            for (int mi = 0; mi < 2; mi++)
                ldsm4(a[mi], qsb + (qa_base + mi * 16 * QW + kw) * 4);
            {
                uint32_t tt[4];
                ldsm4(tt, kbb + (kbuf + kb_base + kw) * 4);
                bf[0][0] = tt[0]; bf[0][1] = tt[1];
                bf[1][0] = tt[2]; bf[1][1] = tt[3];
            }
#pragma unroll
            for (int mi = 0; mi < 2; mi++)
#pragma unroll
                for (int ni = 0; ni < 2; ni++)
                    mma16(sacc[mi][ni], a[mi], bf[ni]);
        }

        // silu + mask + fp16 P store (no 1/S here — deferred to epilogue)
#pragma unroll
        for (int mi = 0; mi < 2; mi++) {
            const int qr = wm * 32 + mi * 16 + g;
            const int qg0 = q0 + qr, qg1 = qg0 + 8;
            const int iq0 = min(qg0, limit), iq1 = min(qg1, limit);
#pragma unroll
            for (int ni = 0; ni < 2; ni++) {
                const int cc = wn * 16 + ni * 8 + 2 * tg;
                const int kg0 = k0 + cc, kg1 = kg0 + 1;
                const int ik0 = min(kg0, limit), ik1 = min(kg1, limit);

                float p00 = ((qg0 == kg0) || (iq0 > ik0)) ? silu_f(sacc[mi][ni][0] * ALPHA_F) : 0.0f;
                float p01 = ((qg0 == kg1) || (iq0 > ik1)) ? silu_f(sacc[mi][ni][1] * ALPHA_F) : 0.0f;
                float p10 = ((qg1 == kg0) || (iq1 > ik0)) ? silu_f(sacc[mi][ni][2] * ALPHA_F) : 0.0f;
                float p11 = ((qg1 == kg1) || (iq1 > ik1)) ? silu_f(sacc[mi][ni][3] * ALPHA_F) : 0.0f;

                const int wofs = wn * 8 + ni * 4 + tg;   // word = cc/2
                psh[qr * PW + wofs]       = h2pack(p00, p01);
                psh[(qr + 8) * PW + wofs] = h2pack(p10, p11);
            }
        }
        __syncthreads();

        // ----- Stage 2 (fp16): O += P @ V, warp tile 32m x 32n -----
#pragma unroll
        for (int ks = 0; ks < 4; ks++) {   // 4 x k16 steps over kv=64
            uint32_t a[2][4], bf[4][2];
#pragma unroll
            for (int mi = 0; mi < 2; mi++)
                ldsm4(a[mi], psb + (pa_base + mi * 16 * PW + ks * 8) * 4);
#pragma unroll
            for (int np = 0; np < 2; np++) {
                uint32_t tt[4];
                ldsm4t(tt, vsb + (vb_base + ks * 16 * QW + np * 8) * 4);
                bf[2 * np][0] = tt[0]; bf[2 * np][1] = tt[1];
                bf[2 * np + 1][0] = tt[2]; bf[2 * np + 1][1] = tt[3];
            }
#pragma unroll
            for (int mi = 0; mi < 2; mi++)
#pragma unroll
                for (int ni = 0; ni < 4; ni++)
                    mma16(oacc[mi][ni], a[mi], bf[ni]);
        }
        __syncthreads();   // all stage2 V/P reads done

        if (t + 1 < ntile) loadV(t + 1);
        CP_COMMIT();
        if (t + 2 < ntile) loadK(t + 2, t & 1);
        CP_COMMIT();
    }

    // Epilogue: scale by 1/S, fp16 attn output
#pragma unroll
    for (int mi = 0; mi < 2; mi++) {
        const int r1 = q0 + wm * 32 + mi * 16 + g;
#pragma unroll
        for (int ni = 0; ni < 4; ni++) {
            const int c = h * D_ + wn * 32 + ni * 8 + 2 * tg;
            *(uint32_t*)&g_attnh[(size_t)(b * S_ + r1) * E_ + c] =
                h2pack(oacc[mi][ni][0] * INV_S_F, oacc[mi][ni][1] * INV_S_F);
            *(uint32_t*)&g_attnh[(size_t)(b * S_ + r1 + 8) * E_ + c] =
                h2pack(oacc[mi][ni][2] * INV_S_F, oacc[mi][ni][3] * INV_S_F);
        }
    }
}

// ---------------------------------------------------------------------------
// Launch
// ---------------------------------------------------------------------------
extern "C" void kernel_launch(void* const* d_in, const int* in_sizes, int n_in,
                              void* d_out, int out_size) {
    const float* x        = (const float*)d_in[0];
    const int*   ntg      = (const int*)d_in[1];
    const float* uvqk_w   = (const float*)d_in[2];
    const float* uvqk_b   = (const float*)d_in[3];
    const float* out_w    = (const float*)d_in[4];
    const float* in_scale = (const float*)d_in[5];
    const float* in_bias  = (const float*)d_in[6];
    const float* out_scale= (const float*)d_in[7];
    const float* out_bias = (const float*)d_in[8];
    float* out = (float*)d_out;

    (void)in_sizes; (void)n_in; (void)out_size;

    static bool attr_set = false;
    if (!attr_set) {
        cudaFuncSetAttribute(attn_tc, cudaFuncAttributeMaxDynamicSharedMemorySize,
                             ATTN_SMEM_BYTES);
        cudaFuncSetAttribute(gemm_uvqk_fp16, cudaFuncAttributeMaxDynamicSharedMemorySize,
                             G1_SMEM);
        cudaFuncSetAttribute(gemm_out_fp16, cudaFuncAttributeMaxDynamicSharedMemorySize,
                             G2_SMEM);
        attr_set = true;
    }

    __half* w1h_ptr; cudaGetSymbolAddress((void**)&w1h_ptr, g_w1h);
    __half* w2h_ptr; cudaGetSymbolAddress((void**)&w2h_ptr, g_w2h);

    transpose_half<<<dim3(E_ / 32, UVQK_ / 32), dim3(32, 8)>>>(uvqk_w, w1h_ptr, E_, UVQK_);
    transpose_half<<<dim3(3072 / 32, E_ / 32), dim3(32, 8)>>>(out_w, w2h_ptr, 3072, E_);

    ln_in_kernel<<<MTOT, 256>>>(x, in_scale, in_bias);
    gemm_uvqk_fp16<<<dim3(UVQK_ / 128, MTOT / 128), 256, G1_SMEM>>>(uvqk_b);
    attn_tc<<<dim3(S_ / 128, H_, B_), 512, ATTN_SMEM_BYTES>>>(ntg);
    ln_attn_kernel<<<MTOT, 256>>>(out_scale, out_bias);
    gemm_out_fp16<<<dim3(E_ / 128, MTOT / 128), 256, G2_SMEM>>>(x, out);
}